// round 13
// baseline (speedup 1.0000x reference)
#include <cuda_runtime.h>
#include <cuda_fp16.h>
#include <cstdint>

#define N_NODES   100000
#define E_PER_REL 150000
#define R_REL     4
#define E_TOTAL   (E_PER_REL * R_REL)
#define MSG_COLS  256
#define ACC_COLS  64

// ---------------------------------------------------------------------------
// Device globals (no runtime allocation allowed)
// ---------------------------------------------------------------------------
__device__ __align__(128) __half g_acc1[(size_t)N_NODES * ACC_COLS];  // 12.8 MB
__device__ __align__(128) __half g_acc2[(size_t)N_NODES * ACC_COLS];  // 12.8 MB
__device__ __align__(128) __half g_msg1[(size_t)N_NODES * MSG_COLS];  // 51.2 MB
__device__ __align__(128) __half g_msg2[(size_t)N_NODES * MSG_COLS];  // 51.2 MB
// Pre-swizzled fp16 weight tiles: [cb*CHUNKS+ch] tiles of 64n x 64k (8192 B)
__device__ __align__(256) __half g_B1[5 * 2 * 64 * 64];
__device__ __align__(256) __half g_B2[5 * 1 * 64 * 64];
// dst-sorted edge structures (rebuilt every launch; deterministic work)
__device__ int g_counts[N_NODES];
__device__ int g_starts[N_NODES + 1];
__device__ int g_cursor[N_NODES];
__device__ int g_elist[E_TOTAL];    // src msg half-offsets, grouped by dst
__device__ int g_idx_is64;

// XOR swizzle on 16B granules within a 128B row: byte offset for (row, k)
__device__ __forceinline__ uint32_t swz(uint32_t row, uint32_t k) {
    uint32_t g = k >> 3;
    return row * 128u + (((g ^ (row & 7u)) << 4) | ((k & 7u) << 1));
}

__device__ __forceinline__ int load_idx(const void* v, int e) {
    return g_idx_is64 ? (int)((const long long*)v)[e] : ((const int*)v)[e];
}

// ---------------------------------------------------------------------------
// zero counts (whole grid) + index-dtype sniff (block 0).
// int64 values < 2^31 => every odd 32-bit word is zero.
// ---------------------------------------------------------------------------
__global__ void zero_sniff_kernel(const unsigned int* __restrict__ idx,
                                  int* __restrict__ counts) {
    int i = blockIdx.x * blockDim.x + threadIdx.x;
    if (i < N_NODES) counts[i] = 0;
    if (blockIdx.x == 0) {
        __shared__ int nz;
        if (threadIdx.x == 0) nz = 0;
        __syncthreads();
        for (int j = threadIdx.x; j < 4096; j += blockDim.x)
            if (idx[2 * j + 1] != 0u) nz = 1;
        __syncthreads();
        if (threadIdx.x == 0) g_idx_is64 = (nz == 0) ? 1 : 0;
    }
}

// ---------------------------------------------------------------------------
// Weight prep helper: combined signed weights -> swizzled fp16 tiles.
// Column c: 0..63 = Wself; 64.. = sign_r * Wrel (r=3 negated).
// ---------------------------------------------------------------------------
__device__ __forceinline__ void prep_one(const float* Wrel, const float* Wself,
                                         __half* B, int din, int chunks, int i) {
    int c = i / din;
    int d = i - c * din;
    float v;
    if (c < 64) {
        v = Wself[d * 64 + c];
    } else {
        int r = (c - 64) >> 6;
        int o = (c - 64) & 63;
        v = Wrel[((size_t)r * din + d) * 64 + o];
        if (r == 3) v = -v;   // SUBTRACT_REL = 3
    }
    int cb = c >> 6, n = c & 63;
    int ch = d >> 6, k = d & 63;
    size_t tile = (size_t)(cb * chunks + ch) * 8192;   // bytes
    *(__half*)((char*)B + tile + swz((uint32_t)n, (uint32_t)k)) = __float2half_rn(v);
}

// ---------------------------------------------------------------------------
// Fused: in-degree count (blocks [0, EB)) + weight prep (blocks [EB, EB+240)).
// ---------------------------------------------------------------------------
#define EB ((E_TOTAL + 255) / 256)       // 2344
#define PREPB ((320 * 128 + 320 * 64 + 255) / 256)   // 240

__global__ void count_prep_kernel(const void* __restrict__ dst_v,
                                  int* __restrict__ counts,
                                  const float* __restrict__ W1, const float* __restrict__ Ws1,
                                  const float* __restrict__ W2, const float* __restrict__ Ws2,
                                  __half* __restrict__ B1, __half* __restrict__ B2) {
    if (blockIdx.x < EB) {
        int e = blockIdx.x * 256 + threadIdx.x;
        if (e < E_TOTAL) atomicAdd(&counts[load_idx(dst_v, e)], 1);
    } else {
        int idx = (blockIdx.x - EB) * 256 + threadIdx.x;
        if (idx < 320 * 128) {
            prep_one(W1, Ws1, B1, 128, 2, idx);
        } else if (idx < 320 * 128 + 320 * 64) {
            prep_one(W2, Ws2, B2, 64, 1, idx - 320 * 128);
        }
    }
}

// ---------------------------------------------------------------------------
// Single-block exclusive scan of counts -> starts & cursor. 1024 threads,
// 98 contiguous counts per thread; two-pass (sum, then prefix writeback).
// ---------------------------------------------------------------------------
#define SCAN_PER 98   // 1024 * 98 = 100352 >= N_NODES

__global__ void __launch_bounds__(1024) scan_all_kernel(const int* __restrict__ counts,
                                                        int* __restrict__ starts,
                                                        int* __restrict__ cursor) {
    __shared__ int s[1024];
    int t = threadIdx.x;
    int base = t * SCAN_PER;

    int sum = 0;
    for (int j = 0; j < SCAN_PER; j++) {
        int i = base + j;
        if (i < N_NODES) sum += __ldg(&counts[i]);
    }
    s[t] = sum;
    __syncthreads();
#pragma unroll
    for (int off = 1; off < 1024; off <<= 1) {
        int v = (t >= off) ? s[t - off] : 0;
        __syncthreads();
        s[t] += v;
        __syncthreads();
    }
    int run = s[t] - sum;   // exclusive prefix for this thread's range
    for (int j = 0; j < SCAN_PER; j++) {
        int i = base + j;
        if (i < N_NODES) {
            starts[i] = run;
            cursor[i] = run;
            run += __ldg(&counts[i]);
        }
    }
    if (t == 0) starts[N_NODES] = E_TOTAL;
}

// ---------------------------------------------------------------------------
__global__ void fill_kernel(const void* __restrict__ src_v, const void* __restrict__ dst_v,
                            int* __restrict__ cursor, int* __restrict__ elist) {
    int e = blockIdx.x * blockDim.x + threadIdx.x;
    if (e >= E_TOTAL) return;
    int r = e / E_PER_REL;
    int s = load_idx(src_v, e);
    int d = load_idx(dst_v, e);
    int pos = atomicAdd(&cursor[d], 1);
    elist[pos] = s * MSG_COLS + r * 64;
}

// ---------------------------------------------------------------------------
__device__ __forceinline__ void mma16816(float* c, const uint32_t* a, uint32_t b0, uint32_t b1) {
    asm volatile("mma.sync.aligned.m16n8k16.row.col.f32.f16.f16.f32 "
                 "{%0,%1,%2,%3}, {%4,%5,%6,%7}, {%8,%9}, {%0,%1,%2,%3};"
                 : "+f"(c[0]), "+f"(c[1]), "+f"(c[2]), "+f"(c[3])
                 : "r"(a[0]), "r"(a[1]), "r"(a[2]), "r"(a[3]), "r"(b0), "r"(b1));
}
__device__ __forceinline__ void ldsm4(uint32_t* r, uint32_t addr) {
    asm volatile("ldmatrix.sync.aligned.m8n8.x4.shared.b16 {%0,%1,%2,%3}, [%4];"
                 : "=r"(r[0]), "=r"(r[1]), "=r"(r[2]), "=r"(r[3]) : "r"(addr));
}

// ---------------------------------------------------------------------------
// Tensor-core GEMM (unchanged). CTA = 128m x 64n; cb = blockIdx.x (0..4).
// AHALF: A already fp16. cb 0 -> acc[N,64]; cb 1..4 -> msg[N,256].
// ---------------------------------------------------------------------------
#define STG_STRIDE 72   // halves per staged row (64 + 8 pad -> 144 B)

template <int CHUNKS, bool AHALF>
__global__ void __launch_bounds__(256, 3) gemm_mma_kernel(const void* __restrict__ A, int lda,
                                                          const __half* __restrict__ B,
                                                          __half* __restrict__ Cacc,
                                                          __half* __restrict__ Cmsg) {
    __shared__ __align__(16) char S[24576];
    __half* Ah  = (__half*)(S);             // 16 KB
    __half* Bhs = (__half*)(S + 16384);     // 8 KB
    __half* stage = (__half*)S;             // reused post-compute (18.4 KB)

    const int tid  = threadIdx.x;
    const int wid  = tid >> 5;
    const int lane = tid & 31;
    const int cb   = blockIdx.x;      // column block (0..4)
    const int m0   = blockIdx.y * 128;
    const int wm   = wid >> 1;
    const int wn   = wid & 1;

    const uint32_t ah_u = (uint32_t)__cvta_generic_to_shared(Ah);
    const uint32_t bh_u = (uint32_t)__cvta_generic_to_shared(Bhs);

    const int tq = lane >> 3;
    const int lr = lane & 7;
    const int a_lrow = lr + (tq & 1) * 8;
    const int a_gad  = (tq >> 1);
    const int b_lr   = lr + (tq >> 1) * 8;
    const int b_gad  = (tq & 1);

    float acc[2][4][4];
#pragma unroll
    for (int mt = 0; mt < 2; mt++)
#pragma unroll
        for (int j = 0; j < 4; j++)
#pragma unroll
            for (int q = 0; q < 4; q++) acc[mt][j][q] = 0.f;

    for (int ch = 0; ch < CHUNKS; ch++) {
        {   // copy pre-swizzled B tile (8 KB)
            size_t tile = (size_t)(cb * CHUNKS + ch) * 8192;
            const uint4* sh = (const uint4*)((const char*)B + tile);
            uint4* dh = (uint4*)Bhs;
            dh[tid] = sh[tid]; dh[tid + 256] = sh[tid + 256];
        }
        // ---- A tile [128m x 64k] into swizzled smem
#pragma unroll
        for (int i = 0; i < 4; i++) {
            int gran = i * 256 + tid;
            int m = gran >> 3;
            int g = gran & 7;
            int gr = m0 + m;
            uint32_t off = swz((uint32_t)m, (uint32_t)(g * 8));
            if (AHALF) {
                uint4 v = make_uint4(0u, 0u, 0u, 0u);
                if (gr < N_NODES)
                    v = *(const uint4*)&((const __half*)A)[(size_t)gr * lda + ch * 64 + g * 8];
                *(uint4*)((char*)Ah + off) = v;
            } else {
                float4 v0 = make_float4(0.f, 0.f, 0.f, 0.f), v1 = v0;
                if (gr < N_NODES) {
                    const float* ap = &((const float*)A)[(size_t)gr * lda + ch * 64 + g * 8];
                    v0 = *(const float4*)ap;
                    v1 = *(const float4*)(ap + 4);
                }
                __half h[8];
                h[0] = __float2half_rn(v0.x); h[1] = __float2half_rn(v0.y);
                h[2] = __float2half_rn(v0.z); h[3] = __float2half_rn(v0.w);
                h[4] = __float2half_rn(v1.x); h[5] = __float2half_rn(v1.y);
                h[6] = __float2half_rn(v1.z); h[7] = __float2half_rn(v1.w);
                *(uint4*)((char*)Ah + off) = *(const uint4*)h;
            }
        }
        __syncthreads();

#pragma unroll
        for (int ks = 0; ks < 4; ks++) {
            uint32_t afh[2][4], bfh[2][4];
#pragma unroll
            for (int mt = 0; mt < 2; mt++) {
                int arow = wm * 32 + mt * 16 + a_lrow;
                uint32_t a_off = arow * 128u +
                                 (((uint32_t)((ks * 2 + a_gad) ^ (arow & 7))) << 4);
                ldsm4(afh[mt], ah_u + a_off);
            }
#pragma unroll
            for (int bt = 0; bt < 2; bt++) {
                int brow = wn * 32 + bt * 16 + b_lr;
                uint32_t b_off = brow * 128u +
                                 (((uint32_t)((ks * 2 + b_gad) ^ (brow & 7))) << 4);
                ldsm4(bfh[bt], bh_u + b_off);
            }
#pragma unroll
            for (int mt = 0; mt < 2; mt++)
#pragma unroll
                for (int bt = 0; bt < 2; bt++) {
                    mma16816(acc[mt][bt * 2 + 0], afh[mt], bfh[bt][0], bfh[bt][1]);
                    mma16816(acc[mt][bt * 2 + 1], afh[mt], bfh[bt][2], bfh[bt][3]);
                }
        }
        __syncthreads();
    }

    // ---- Unified fp16 epilogue: stage, then coalesced 16B stores
    const int ccol = (lane & 3) * 2;
#pragma unroll
    for (int mt = 0; mt < 2; mt++) {
        int lrow0 = wm * 32 + mt * 16 + (lane >> 2);
#pragma unroll
        for (int j = 0; j < 4; j++) {
            int lc = wn * 32 + j * 8 + ccol;
            *(__half2*)&stage[lrow0 * STG_STRIDE + lc] =
                __floats2half2_rn(acc[mt][j][0], acc[mt][j][1]);
            *(__half2*)&stage[(lrow0 + 8) * STG_STRIDE + lc] =
                __floats2half2_rn(acc[mt][j][2], acc[mt][j][3]);
        }
    }
    __syncthreads();
    __half* dstbuf = (cb == 0) ? Cacc : Cmsg;
    const int dstride = (cb == 0) ? ACC_COLS : MSG_COLS;
    const int mbase = (cb == 0) ? 0 : (cb - 1) * 64;
#pragma unroll
    for (int i = 0; i < 4; i++) {
        int chunk = i * 256 + tid;
        int row = chunk >> 3;
        int cc  = chunk & 7;
        int gr = m0 + row;
        if (gr < N_NODES) {
            uint4 v = *(const uint4*)&stage[row * STG_STRIDE + cc * 8];
            *(uint4*)&dstbuf[(size_t)gr * dstride + mbase + cc * 8] = v;
        }
    }
}

// ---------------------------------------------------------------------------
// Aggregate: total = acc[n] + sum msg[elist[i]].  4-deep unrolled gathers.
// MODE 0: write fp16 acc with relu (layer 1).
// MODE 1: write f32 out with relu+sigmoid (layer 2, fused epilogue).
// ---------------------------------------------------------------------------
__device__ __forceinline__ void add8(float4& a0, float4& a1, uint4 g) {
    __half2* h = (__half2*)&g;
    float2 f0 = __half22float2(h[0]), f1 = __half22float2(h[1]);
    float2 f2 = __half22float2(h[2]), f3 = __half22float2(h[3]);
    a0.x += f0.x; a0.y += f0.y; a0.z += f1.x; a0.w += f1.y;
    a1.x += f2.x; a1.y += f2.y; a1.z += f3.x; a1.w += f3.y;
}

template <int MODE>
__global__ void __launch_bounds__(256) agg_kernel(const int* __restrict__ starts,
                                                  const int* __restrict__ elist,
                                                  const __half* __restrict__ msg,
                                                  __half* __restrict__ acc,
                                                  float* __restrict__ out) {
    int gid = blockIdx.x * blockDim.x + threadIdx.x;
    int n   = gid >> 3;
    if (n >= N_NODES) return;
    int sub = gid & 7;

    int beg = __ldg(&starts[n]);
    int end = __ldg(&starts[n + 1]);

    __half* ap = &acc[(size_t)n * ACC_COLS + sub * 8];
    uint4 aw = *(const uint4*)ap;
    float4 a0 = make_float4(0.f, 0.f, 0.f, 0.f), a1 = a0;
    add8(a0, a1, aw);   // self-path from gemm cb0

    int i = beg;
    for (; i + 3 < end; i += 4) {
        int o0 = __ldg(&elist[i]);
        int o1 = __ldg(&elist[i + 1]);
        int o2 = __ldg(&elist[i + 2]);
        int o3 = __ldg(&elist[i + 3]);
        uint4 g0 = *(const uint4*)&msg[(size_t)o0 + sub * 8];
        uint4 g1 = *(const uint4*)&msg[(size_t)o1 + sub * 8];
        uint4 g2 = *(const uint4*)&msg[(size_t)o2 + sub * 8];
        uint4 g3 = *(const uint4*)&msg[(size_t)o3 + sub * 8];
        add8(a0, a1, g0); add8(a0, a1, g1);
        add8(a0, a1, g2); add8(a0, a1, g3);
    }
    for (; i < end; i++) {
        int o0 = __ldg(&elist[i]);
        uint4 g0 = *(const uint4*)&msg[(size_t)o0 + sub * 8];
        add8(a0, a1, g0);
    }

    a0.x = fmaxf(a0.x, 0.f); a0.y = fmaxf(a0.y, 0.f);
    a0.z = fmaxf(a0.z, 0.f); a0.w = fmaxf(a0.w, 0.f);
    a1.x = fmaxf(a1.x, 0.f); a1.y = fmaxf(a1.y, 0.f);
    a1.z = fmaxf(a1.z, 0.f); a1.w = fmaxf(a1.w, 0.f);

    if (MODE == 0) {
        __half h[8];
        h[0] = __float2half_rn(a0.x); h[1] = __float2half_rn(a0.y);
        h[2] = __float2half_rn(a0.z); h[3] = __float2half_rn(a0.w);
        h[4] = __float2half_rn(a1.x); h[5] = __float2half_rn(a1.y);
        h[6] = __float2half_rn(a1.z); h[7] = __float2half_rn(a1.w);
        *(uint4*)ap = *(const uint4*)h;
    } else {
        float r[8] = {a0.x, a0.y, a0.z, a0.w, a1.x, a1.y, a1.z, a1.w};
#pragma unroll
        for (int j = 0; j < 8; j++)
            r[j] = 1.f / (1.f + __expf(-r[j]));
        float4* op = (float4*)&out[(size_t)n * ACC_COLS + sub * 8];
        op[0] = make_float4(r[0], r[1], r[2], r[3]);
        op[1] = make_float4(r[4], r[5], r[6], r[7]);
    }
}

// ---------------------------------------------------------------------------
extern "C" void kernel_launch(void* const* d_in, const int* in_sizes, int n_in,
                              void* d_out, int out_size) {
    const float* node_emb = (const float*)d_in[0];
    const void*  src      = d_in[1];
    const void*  dst      = d_in[2];
    const float* W1       = (const float*)d_in[3];
    const float* Wself1   = (const float*)d_in[4];
    const float* W2       = (const float*)d_in[5];
    const float* Wself2   = (const float*)d_in[6];
    float*       out      = (float*)d_out;

    __half *acc1, *acc2, *msg1, *msg2, *B1, *B2;
    int *counts, *starts, *cursor, *elist;
    cudaGetSymbolAddress((void**)&acc1, g_acc1);
    cudaGetSymbolAddress((void**)&acc2, g_acc2);
    cudaGetSymbolAddress((void**)&msg1, g_msg1);
    cudaGetSymbolAddress((void**)&msg2, g_msg2);
    cudaGetSymbolAddress((void**)&B1, g_B1);
    cudaGetSymbolAddress((void**)&B2, g_B2);
    cudaGetSymbolAddress((void**)&counts, g_counts);
    cudaGetSymbolAddress((void**)&starts, g_starts);
    cudaGetSymbolAddress((void**)&cursor, g_cursor);
    cudaGetSymbolAddress((void**)&elist, g_elist);

    // ---- edge-list build: 4 launches total
    zero_sniff_kernel<<<(N_NODES + 255) / 256, 256>>>((const unsigned int*)src, counts);
    count_prep_kernel<<<EB + PREPB, 256>>>(dst, counts, W1, Wself1, W2, Wself2, B1, B2);
    scan_all_kernel<<<1, 1024>>>(counts, starts, cursor);
    fill_kernel<<<EB, 256>>>(src, dst, cursor, elist);

    const int mblocks = (N_NODES + 127) / 128;             // 782
    const int ablocks = (N_NODES * 8 + 255) / 256;         // 3125

    // Layer 1: acc1/msg1 = node_emb @ Wc1; aggregate + relu into acc1 (fp16)
    gemm_mma_kernel<2, false><<<dim3(5, mblocks), 256>>>(node_emb, 128, B1, acc1, msg1);
    agg_kernel<0><<<ablocks, 256>>>(starts, elist, msg1, acc1, nullptr);

    // Layer 2: acc2/msg2 = acc1(fp16) @ Wc2; aggregate + relu + sigmoid -> out
    gemm_mma_kernel<1, true><<<dim3(5, mblocks), 256>>>(acc1, ACC_COLS, B2, acc2, msg2);
    agg_kernel<1><<<ablocks, 256>>>(starts, elist, msg2, acc2, out);
}

// round 14
// speedup vs baseline: 1.9283x; 1.9283x over previous
#include <cuda_runtime.h>
#include <cuda_fp16.h>
#include <cstdint>

#define N_NODES   100000
#define E_PER_REL 150000
#define R_REL     4
#define E_TOTAL   (E_PER_REL * R_REL)
#define MSG_COLS  256
#define ACC_COLS  64

// ---------------------------------------------------------------------------
// Device globals (no runtime allocation allowed)
// ---------------------------------------------------------------------------
__device__ __align__(128) __half g_acc1[(size_t)N_NODES * ACC_COLS];  // 12.8 MB
__device__ __align__(128) __half g_acc2[(size_t)N_NODES * ACC_COLS];  // 12.8 MB
__device__ __align__(128) __half g_msg1[(size_t)N_NODES * MSG_COLS];  // 51.2 MB
__device__ __align__(128) __half g_msg2[(size_t)N_NODES * MSG_COLS];  // 51.2 MB
// Pre-swizzled fp16 weight tiles: [cb*CHUNKS+ch] tiles of 64n x 64k (8192 B)
__device__ __align__(256) __half g_B1[5 * 2 * 64 * 64];
__device__ __align__(256) __half g_B2[5 * 1 * 64 * 64];
// dst-sorted edge structures (rebuilt every launch; deterministic work)
__device__ int g_counts[N_NODES];
__device__ int g_starts[N_NODES + 1];
__device__ int g_cursor[N_NODES];
__device__ int g_bsum[128];
__device__ int g_elist[E_TOTAL];    // src msg half-offsets, grouped by dst
__device__ int g_idx_is64;

// XOR swizzle on 16B granules within a 128B row: byte offset for (row, k)
__device__ __forceinline__ uint32_t swz(uint32_t row, uint32_t k) {
    uint32_t g = k >> 3;
    return row * 128u + (((g ^ (row & 7u)) << 4) | ((k & 7u) << 1));
}

__device__ __forceinline__ int load_idx(const void* v, int e) {
    return g_idx_is64 ? (int)((const long long*)v)[e] : ((const int*)v)[e];
}

// ---------------------------------------------------------------------------
// zero counts (whole grid) + index-dtype sniff (block 0).
// int64 values < 2^31 => every odd 32-bit word is zero.
// ---------------------------------------------------------------------------
__global__ void zero_sniff_kernel(const unsigned int* __restrict__ idx,
                                  int* __restrict__ counts) {
    int i = blockIdx.x * blockDim.x + threadIdx.x;
    if (i < N_NODES) counts[i] = 0;
    if (blockIdx.x == 0) {
        __shared__ int nz;
        if (threadIdx.x == 0) nz = 0;
        __syncthreads();
        for (int j = threadIdx.x; j < 4096; j += blockDim.x)
            if (idx[2 * j + 1] != 0u) nz = 1;
        __syncthreads();
        if (threadIdx.x == 0) g_idx_is64 = (nz == 0) ? 1 : 0;
    }
}

// ---------------------------------------------------------------------------
// Weight prep helper: combined signed weights -> swizzled fp16 tiles.
// Column c: 0..63 = Wself; 64.. = sign_r * Wrel (r=3 negated).
// ---------------------------------------------------------------------------
__device__ __forceinline__ void prep_one(const float* Wrel, const float* Wself,
                                         __half* B, int din, int chunks, int i) {
    int c = i / din;
    int d = i - c * din;
    float v;
    if (c < 64) {
        v = Wself[d * 64 + c];
    } else {
        int r = (c - 64) >> 6;
        int o = (c - 64) & 63;
        v = Wrel[((size_t)r * din + d) * 64 + o];
        if (r == 3) v = -v;   // SUBTRACT_REL = 3
    }
    int cb = c >> 6, n = c & 63;
    int ch = d >> 6, k = d & 63;
    size_t tile = (size_t)(cb * chunks + ch) * 8192;   // bytes
    *(__half*)((char*)B + tile + swz((uint32_t)n, (uint32_t)k)) = __float2half_rn(v);
}

// ---------------------------------------------------------------------------
// Fused: in-degree count (blocks [0, EB)) + weight prep (blocks [EB, EB+240)).
// ---------------------------------------------------------------------------
#define EB ((E_TOTAL + 255) / 256)                   // 2344
#define PREPB ((320 * 128 + 320 * 64 + 255) / 256)   // 240

__global__ void count_prep_kernel(const void* __restrict__ dst_v,
                                  int* __restrict__ counts,
                                  const float* __restrict__ W1, const float* __restrict__ Ws1,
                                  const float* __restrict__ W2, const float* __restrict__ Ws2,
                                  __half* __restrict__ B1, __half* __restrict__ B2) {
    if (blockIdx.x < EB) {
        int e = blockIdx.x * 256 + threadIdx.x;
        if (e < E_TOTAL) atomicAdd(&counts[load_idx(dst_v, e)], 1);
    } else {
        int idx = (blockIdx.x - EB) * 256 + threadIdx.x;
        if (idx < 320 * 128) {
            prep_one(W1, Ws1, B1, 128, 2, idx);
        } else if (idx < 320 * 128 + 320 * 64) {
            prep_one(W2, Ws2, B2, 64, 1, idx - 320 * 128);
        }
    }
}

// ---------------------------------------------------------------------------
// 3-kernel scan (round-12 proven version): per-block scan across 98 SMs,
// then block-sum scan, then add-back + cursor init.
// ---------------------------------------------------------------------------
__global__ void scan1_kernel(const int* __restrict__ counts, int* __restrict__ starts,
                             int* __restrict__ bsum) {
    __shared__ int s[256];
    int base = blockIdx.x * 1024 + threadIdx.x * 4;
    int c[4], t = 0;
#pragma unroll
    for (int j = 0; j < 4; j++) {
        c[j] = (base + j < N_NODES) ? counts[base + j] : 0;
        t += c[j];
    }
    s[threadIdx.x] = t;
    __syncthreads();
#pragma unroll
    for (int off = 1; off < 256; off <<= 1) {
        int v = (threadIdx.x >= off) ? s[threadIdx.x - off] : 0;
        __syncthreads();
        s[threadIdx.x] += v;
        __syncthreads();
    }
    int run = s[threadIdx.x] - t;   // exclusive prefix for this thread
#pragma unroll
    for (int j = 0; j < 4; j++) {
        if (base + j < N_NODES) starts[base + j] = run;
        run += c[j];
    }
    if (threadIdx.x == 255) bsum[blockIdx.x] = s[255];
}

__global__ void scan2_kernel(int* __restrict__ bsum, int nb) {
    __shared__ int s[128];
    int t = threadIdx.x;
    int v = (t < nb) ? bsum[t] : 0;
    s[t] = v;
    __syncthreads();
#pragma unroll
    for (int off = 1; off < 128; off <<= 1) {
        int u = (t >= off) ? s[t - off] : 0;
        __syncthreads();
        s[t] += u;
        __syncthreads();
    }
    if (t < nb) bsum[t] = s[t] - v;   // exclusive
}

__global__ void scan3_kernel(int* __restrict__ starts, int* __restrict__ cursor,
                             const int* __restrict__ bsum) {
    int i = blockIdx.x * blockDim.x + threadIdx.x;
    if (i < N_NODES) {
        int v = starts[i] + bsum[i >> 10];
        starts[i] = v;
        cursor[i] = v;
    }
    if (i == N_NODES) starts[N_NODES] = E_TOTAL;
}

// ---------------------------------------------------------------------------
__global__ void fill_kernel(const void* __restrict__ src_v, const void* __restrict__ dst_v,
                            int* __restrict__ cursor, int* __restrict__ elist) {
    int e = blockIdx.x * blockDim.x + threadIdx.x;
    if (e >= E_TOTAL) return;
    int r = e / E_PER_REL;
    int s = load_idx(src_v, e);
    int d = load_idx(dst_v, e);
    int pos = atomicAdd(&cursor[d], 1);
    elist[pos] = s * MSG_COLS + r * 64;
}

// ---------------------------------------------------------------------------
__device__ __forceinline__ void mma16816(float* c, const uint32_t* a, uint32_t b0, uint32_t b1) {
    asm volatile("mma.sync.aligned.m16n8k16.row.col.f32.f16.f16.f32 "
                 "{%0,%1,%2,%3}, {%4,%5,%6,%7}, {%8,%9}, {%0,%1,%2,%3};"
                 : "+f"(c[0]), "+f"(c[1]), "+f"(c[2]), "+f"(c[3])
                 : "r"(a[0]), "r"(a[1]), "r"(a[2]), "r"(a[3]), "r"(b0), "r"(b1));
}
__device__ __forceinline__ void ldsm4(uint32_t* r, uint32_t addr) {
    asm volatile("ldmatrix.sync.aligned.m8n8.x4.shared.b16 {%0,%1,%2,%3}, [%4];"
                 : "=r"(r[0]), "=r"(r[1]), "=r"(r[2]), "=r"(r[3]) : "r"(addr));
}

// ---------------------------------------------------------------------------
// Tensor-core GEMM (unchanged). CTA = 128m x 64n; cb = blockIdx.x (0..4).
// AHALF: A already fp16. cb 0 -> acc[N,64]; cb 1..4 -> msg[N,256].
// ---------------------------------------------------------------------------
#define STG_STRIDE 72   // halves per staged row (64 + 8 pad -> 144 B)

template <int CHUNKS, bool AHALF>
__global__ void __launch_bounds__(256, 3) gemm_mma_kernel(const void* __restrict__ A, int lda,
                                                          const __half* __restrict__ B,
                                                          __half* __restrict__ Cacc,
                                                          __half* __restrict__ Cmsg) {
    __shared__ __align__(16) char S[24576];
    __half* Ah  = (__half*)(S);             // 16 KB
    __half* Bhs = (__half*)(S + 16384);     // 8 KB
    __half* stage = (__half*)S;             // reused post-compute (18.4 KB)

    const int tid  = threadIdx.x;
    const int wid  = tid >> 5;
    const int lane = tid & 31;
    const int cb   = blockIdx.x;      // column block (0..4)
    const int m0   = blockIdx.y * 128;
    const int wm   = wid >> 1;
    const int wn   = wid & 1;

    const uint32_t ah_u = (uint32_t)__cvta_generic_to_shared(Ah);
    const uint32_t bh_u = (uint32_t)__cvta_generic_to_shared(Bhs);

    const int tq = lane >> 3;
    const int lr = lane & 7;
    const int a_lrow = lr + (tq & 1) * 8;
    const int a_gad  = (tq >> 1);
    const int b_lr   = lr + (tq >> 1) * 8;
    const int b_gad  = (tq & 1);

    float acc[2][4][4];
#pragma unroll
    for (int mt = 0; mt < 2; mt++)
#pragma unroll
        for (int j = 0; j < 4; j++)
#pragma unroll
            for (int q = 0; q < 4; q++) acc[mt][j][q] = 0.f;

    for (int ch = 0; ch < CHUNKS; ch++) {
        {   // copy pre-swizzled B tile (8 KB)
            size_t tile = (size_t)(cb * CHUNKS + ch) * 8192;
            const uint4* sh = (const uint4*)((const char*)B + tile);
            uint4* dh = (uint4*)Bhs;
            dh[tid] = sh[tid]; dh[tid + 256] = sh[tid + 256];
        }
        // ---- A tile [128m x 64k] into swizzled smem
#pragma unroll
        for (int i = 0; i < 4; i++) {
            int gran = i * 256 + tid;
            int m = gran >> 3;
            int g = gran & 7;
            int gr = m0 + m;
            uint32_t off = swz((uint32_t)m, (uint32_t)(g * 8));
            if (AHALF) {
                uint4 v = make_uint4(0u, 0u, 0u, 0u);
                if (gr < N_NODES)
                    v = *(const uint4*)&((const __half*)A)[(size_t)gr * lda + ch * 64 + g * 8];
                *(uint4*)((char*)Ah + off) = v;
            } else {
                float4 v0 = make_float4(0.f, 0.f, 0.f, 0.f), v1 = v0;
                if (gr < N_NODES) {
                    const float* ap = &((const float*)A)[(size_t)gr * lda + ch * 64 + g * 8];
                    v0 = *(const float4*)ap;
                    v1 = *(const float4*)(ap + 4);
                }
                __half h[8];
                h[0] = __float2half_rn(v0.x); h[1] = __float2half_rn(v0.y);
                h[2] = __float2half_rn(v0.z); h[3] = __float2half_rn(v0.w);
                h[4] = __float2half_rn(v1.x); h[5] = __float2half_rn(v1.y);
                h[6] = __float2half_rn(v1.z); h[7] = __float2half_rn(v1.w);
                *(uint4*)((char*)Ah + off) = *(const uint4*)h;
            }
        }
        __syncthreads();

#pragma unroll
        for (int ks = 0; ks < 4; ks++) {
            uint32_t afh[2][4], bfh[2][4];
#pragma unroll
            for (int mt = 0; mt < 2; mt++) {
                int arow = wm * 32 + mt * 16 + a_lrow;
                uint32_t a_off = arow * 128u +
                                 (((uint32_t)((ks * 2 + a_gad) ^ (arow & 7))) << 4);
                ldsm4(afh[mt], ah_u + a_off);
            }
#pragma unroll
            for (int bt = 0; bt < 2; bt++) {
                int brow = wn * 32 + bt * 16 + b_lr;
                uint32_t b_off = brow * 128u +
                                 (((uint32_t)((ks * 2 + b_gad) ^ (brow & 7))) << 4);
                ldsm4(bfh[bt], bh_u + b_off);
            }
#pragma unroll
            for (int mt = 0; mt < 2; mt++)
#pragma unroll
                for (int bt = 0; bt < 2; bt++) {
                    mma16816(acc[mt][bt * 2 + 0], afh[mt], bfh[bt][0], bfh[bt][1]);
                    mma16816(acc[mt][bt * 2 + 1], afh[mt], bfh[bt][2], bfh[bt][3]);
                }
        }
        __syncthreads();
    }

    // ---- Unified fp16 epilogue: stage, then coalesced 16B stores
    const int ccol = (lane & 3) * 2;
#pragma unroll
    for (int mt = 0; mt < 2; mt++) {
        int lrow0 = wm * 32 + mt * 16 + (lane >> 2);
#pragma unroll
        for (int j = 0; j < 4; j++) {
            int lc = wn * 32 + j * 8 + ccol;
            *(__half2*)&stage[lrow0 * STG_STRIDE + lc] =
                __floats2half2_rn(acc[mt][j][0], acc[mt][j][1]);
            *(__half2*)&stage[(lrow0 + 8) * STG_STRIDE + lc] =
                __floats2half2_rn(acc[mt][j][2], acc[mt][j][3]);
        }
    }
    __syncthreads();
    __half* dstbuf = (cb == 0) ? Cacc : Cmsg;
    const int dstride = (cb == 0) ? ACC_COLS : MSG_COLS;
    const int mbase = (cb == 0) ? 0 : (cb - 1) * 64;
#pragma unroll
    for (int i = 0; i < 4; i++) {
        int chunk = i * 256 + tid;
        int row = chunk >> 3;
        int cc  = chunk & 7;
        int gr = m0 + row;
        if (gr < N_NODES) {
            uint4 v = *(const uint4*)&stage[row * STG_STRIDE + cc * 8];
            *(uint4*)&dstbuf[(size_t)gr * dstride + mbase + cc * 8] = v;
        }
    }
}

// ---------------------------------------------------------------------------
// Aggregate: total = acc[n] + sum msg[elist[i]].  4-deep unrolled gathers.
// MODE 0: write fp16 acc with relu (layer 1).
// MODE 1: write f32 out with relu+sigmoid (layer 2, fused epilogue).
// ---------------------------------------------------------------------------
__device__ __forceinline__ void add8(float4& a0, float4& a1, uint4 g) {
    __half2* h = (__half2*)&g;
    float2 f0 = __half22float2(h[0]), f1 = __half22float2(h[1]);
    float2 f2 = __half22float2(h[2]), f3 = __half22float2(h[3]);
    a0.x += f0.x; a0.y += f0.y; a0.z += f1.x; a0.w += f1.y;
    a1.x += f2.x; a1.y += f2.y; a1.z += f3.x; a1.w += f3.y;
}

template <int MODE>
__global__ void __launch_bounds__(256) agg_kernel(const int* __restrict__ starts,
                                                  const int* __restrict__ elist,
                                                  const __half* __restrict__ msg,
                                                  __half* __restrict__ acc,
                                                  float* __restrict__ out) {
    int gid = blockIdx.x * blockDim.x + threadIdx.x;
    int n   = gid >> 3;
    if (n >= N_NODES) return;
    int sub = gid & 7;

    int beg = __ldg(&starts[n]);
    int end = __ldg(&starts[n + 1]);

    __half* ap = &acc[(size_t)n * ACC_COLS + sub * 8];
    uint4 aw = *(const uint4*)ap;
    float4 a0 = make_float4(0.f, 0.f, 0.f, 0.f), a1 = a0;
    add8(a0, a1, aw);   // self-path from gemm cb0

    int i = beg;
    for (; i + 3 < end; i += 4) {
        int o0 = __ldg(&elist[i]);
        int o1 = __ldg(&elist[i + 1]);
        int o2 = __ldg(&elist[i + 2]);
        int o3 = __ldg(&elist[i + 3]);
        uint4 g0 = *(const uint4*)&msg[(size_t)o0 + sub * 8];
        uint4 g1 = *(const uint4*)&msg[(size_t)o1 + sub * 8];
        uint4 g2 = *(const uint4*)&msg[(size_t)o2 + sub * 8];
        uint4 g3 = *(const uint4*)&msg[(size_t)o3 + sub * 8];
        add8(a0, a1, g0); add8(a0, a1, g1);
        add8(a0, a1, g2); add8(a0, a1, g3);
    }
    for (; i < end; i++) {
        int o0 = __ldg(&elist[i]);
        uint4 g0 = *(const uint4*)&msg[(size_t)o0 + sub * 8];
        add8(a0, a1, g0);
    }

    a0.x = fmaxf(a0.x, 0.f); a0.y = fmaxf(a0.y, 0.f);
    a0.z = fmaxf(a0.z, 0.f); a0.w = fmaxf(a0.w, 0.f);
    a1.x = fmaxf(a1.x, 0.f); a1.y = fmaxf(a1.y, 0.f);
    a1.z = fmaxf(a1.z, 0.f); a1.w = fmaxf(a1.w, 0.f);

    if (MODE == 0) {
        __half h[8];
        h[0] = __float2half_rn(a0.x); h[1] = __float2half_rn(a0.y);
        h[2] = __float2half_rn(a0.z); h[3] = __float2half_rn(a0.w);
        h[4] = __float2half_rn(a1.x); h[5] = __float2half_rn(a1.y);
        h[6] = __float2half_rn(a1.z); h[7] = __float2half_rn(a1.w);
        *(uint4*)ap = *(const uint4*)h;
    } else {
        float r[8] = {a0.x, a0.y, a0.z, a0.w, a1.x, a1.y, a1.z, a1.w};
#pragma unroll
        for (int j = 0; j < 8; j++)
            r[j] = 1.f / (1.f + __expf(-r[j]));
        float4* op = (float4*)&out[(size_t)n * ACC_COLS + sub * 8];
        op[0] = make_float4(r[0], r[1], r[2], r[3]);
        op[1] = make_float4(r[4], r[5], r[6], r[7]);
    }
}

// ---------------------------------------------------------------------------
extern "C" void kernel_launch(void* const* d_in, const int* in_sizes, int n_in,
                              void* d_out, int out_size) {
    const float* node_emb = (const float*)d_in[0];
    const void*  src      = d_in[1];
    const void*  dst      = d_in[2];
    const float* W1       = (const float*)d_in[3];
    const float* Wself1   = (const float*)d_in[4];
    const float* W2       = (const float*)d_in[5];
    const float* Wself2   = (const float*)d_in[6];
    float*       out      = (float*)d_out;

    __half *acc1, *acc2, *msg1, *msg2, *B1, *B2;
    int *counts, *starts, *cursor, *bsum, *elist;
    cudaGetSymbolAddress((void**)&acc1, g_acc1);
    cudaGetSymbolAddress((void**)&acc2, g_acc2);
    cudaGetSymbolAddress((void**)&msg1, g_msg1);
    cudaGetSymbolAddress((void**)&msg2, g_msg2);
    cudaGetSymbolAddress((void**)&B1, g_B1);
    cudaGetSymbolAddress((void**)&B2, g_B2);
    cudaGetSymbolAddress((void**)&counts, g_counts);
    cudaGetSymbolAddress((void**)&starts, g_starts);
    cudaGetSymbolAddress((void**)&cursor, g_cursor);
    cudaGetSymbolAddress((void**)&bsum, g_bsum);
    cudaGetSymbolAddress((void**)&elist, g_elist);

    const int nb1024 = (N_NODES + 1023) / 1024;   // 98

    // ---- edge-list build (6 launches)
    zero_sniff_kernel<<<(N_NODES + 255) / 256, 256>>>((const unsigned int*)src, counts);
    count_prep_kernel<<<EB + PREPB, 256>>>(dst, counts, W1, Wself1, W2, Wself2, B1, B2);
    scan1_kernel<<<nb1024, 256>>>(counts, starts, bsum);
    scan2_kernel<<<1, 128>>>(bsum, nb1024);
    scan3_kernel<<<(N_NODES + 256) / 256, 256>>>(starts, cursor, bsum);
    fill_kernel<<<EB, 256>>>(src, dst, cursor, elist);

    const int mblocks = (N_NODES + 127) / 128;             // 782
    const int ablocks = (N_NODES * 8 + 255) / 256;         // 3125

    // Layer 1: acc1/msg1 = node_emb @ Wc1; aggregate + relu into acc1 (fp16)
    gemm_mma_kernel<2, false><<<dim3(5, mblocks), 256>>>(node_emb, 128, B1, acc1, msg1);
    agg_kernel<0><<<ablocks, 256>>>(starts, elist, msg1, acc1, nullptr);

    // Layer 2: acc2/msg2 = acc1(fp16) @ Wc2; aggregate + relu + sigmoid -> out
    gemm_mma_kernel<1, true><<<dim3(5, mblocks), 256>>>(acc1, ACC_COLS, B2, acc2, msg2);
    agg_kernel<1><<<ablocks, 256>>>(starts, elist, msg2, acc2, out);
}

// round 15
// speedup vs baseline: 2.2288x; 1.1558x over previous
#include <cuda_runtime.h>
#include <cuda_fp16.h>
#include <cstdint>

#define N_NODES   100000
#define E_PER_REL 150000
#define R_REL     4
#define E_TOTAL   (E_PER_REL * R_REL)
#define MSG_COLS  256
#define ACC_COLS  64

// ---------------------------------------------------------------------------
// Device globals (no runtime allocation allowed)
// ---------------------------------------------------------------------------
__device__ __align__(128) __half g_emb[(size_t)N_NODES * 128];        // 25.6 MB (fp16 node_emb)
__device__ __align__(128) __half g_acc1[(size_t)N_NODES * ACC_COLS];  // 12.8 MB
__device__ __align__(128) __half g_acc2[(size_t)N_NODES * ACC_COLS];  // 12.8 MB
__device__ __align__(128) __half g_msg1[(size_t)N_NODES * MSG_COLS];  // 51.2 MB
__device__ __align__(128) __half g_msg2[(size_t)N_NODES * MSG_COLS];  // 51.2 MB
// Pre-swizzled fp16 weight tiles: [cb*CHUNKS+ch] tiles of 64n x 64k (8192 B)
__device__ __align__(256) __half g_B1[5 * 2 * 64 * 64];
__device__ __align__(256) __half g_B2[5 * 1 * 64 * 64];
// dst-sorted edge structures (rebuilt every launch; deterministic work)
__device__ int g_counts[N_NODES];
__device__ int g_starts[N_NODES + 1];
__device__ int g_cursor[N_NODES];
__device__ int g_bsum[128];
__device__ int g_elist[E_TOTAL];    // src msg half-offsets, grouped by dst
__device__ int g_idx_is64;

// XOR swizzle on 16B granules within a 128B row: byte offset for (row, k)
__device__ __forceinline__ uint32_t swz(uint32_t row, uint32_t k) {
    uint32_t g = k >> 3;
    return row * 128u + (((g ^ (row & 7u)) << 4) | ((k & 7u) << 1));
}

__device__ __forceinline__ int load_idx(const void* v, int e) {
    return g_idx_is64 ? (int)((const long long*)v)[e] : ((const int*)v)[e];
}

// ---------------------------------------------------------------------------
// Fused: zero counts + dtype sniff (blocks [0, ZB)) and node_emb f32->fp16
// convert (blocks [ZB, ZB+CONVB)).
// ---------------------------------------------------------------------------
#define ZB ((N_NODES + 255) / 256)           // 391
#define CONVB ((N_NODES * 16 + 255) / 256)   // 6250  (N*128 elems / 8 per thread)

__global__ void zero_sniff_conv_kernel(const unsigned int* __restrict__ idx,
                                       int* __restrict__ counts,
                                       const float* __restrict__ emb_f32,
                                       __half* __restrict__ emb_f16) {
    if (blockIdx.x < ZB) {
        int i = blockIdx.x * 256 + threadIdx.x;
        if (i < N_NODES) counts[i] = 0;
        if (blockIdx.x == 0) {
            __shared__ int nz;
            if (threadIdx.x == 0) nz = 0;
            __syncthreads();
            for (int j = threadIdx.x; j < 4096; j += blockDim.x)
                if (idx[2 * j + 1] != 0u) nz = 1;
            __syncthreads();
            if (threadIdx.x == 0) g_idx_is64 = (nz == 0) ? 1 : 0;
        }
    } else {
        int t = (blockIdx.x - ZB) * 256 + threadIdx.x;   // granule of 8 elems
        if (t < N_NODES * 16) {
            const float* ap = &emb_f32[(size_t)t * 8];
            float4 v0 = *(const float4*)ap;
            float4 v1 = *(const float4*)(ap + 4);
            __half h[8];
            h[0] = __float2half_rn(v0.x); h[1] = __float2half_rn(v0.y);
            h[2] = __float2half_rn(v0.z); h[3] = __float2half_rn(v0.w);
            h[4] = __float2half_rn(v1.x); h[5] = __float2half_rn(v1.y);
            h[6] = __float2half_rn(v1.z); h[7] = __float2half_rn(v1.w);
            *(uint4*)&emb_f16[(size_t)t * 8] = *(const uint4*)h;
        }
    }
}

// ---------------------------------------------------------------------------
// Weight prep helper: combined signed weights -> swizzled fp16 tiles.
// Column c: 0..63 = Wself; 64.. = sign_r * Wrel (r=3 negated).
// ---------------------------------------------------------------------------
__device__ __forceinline__ void prep_one(const float* Wrel, const float* Wself,
                                         __half* B, int din, int chunks, int i) {
    int c = i / din;
    int d = i - c * din;
    float v;
    if (c < 64) {
        v = Wself[d * 64 + c];
    } else {
        int r = (c - 64) >> 6;
        int o = (c - 64) & 63;
        v = Wrel[((size_t)r * din + d) * 64 + o];
        if (r == 3) v = -v;   // SUBTRACT_REL = 3
    }
    int cb = c >> 6, n = c & 63;
    int ch = d >> 6, k = d & 63;
    size_t tile = (size_t)(cb * chunks + ch) * 8192;   // bytes
    *(__half*)((char*)B + tile + swz((uint32_t)n, (uint32_t)k)) = __float2half_rn(v);
}

// ---------------------------------------------------------------------------
// Fused: in-degree count (blocks [0, EB)) + weight prep (blocks [EB, EB+240)).
// ---------------------------------------------------------------------------
#define EB ((E_TOTAL + 255) / 256)                   // 2344
#define PREPB ((320 * 128 + 320 * 64 + 255) / 256)   // 240

__global__ void count_prep_kernel(const void* __restrict__ dst_v,
                                  int* __restrict__ counts,
                                  const float* __restrict__ W1, const float* __restrict__ Ws1,
                                  const float* __restrict__ W2, const float* __restrict__ Ws2,
                                  __half* __restrict__ B1, __half* __restrict__ B2) {
    if (blockIdx.x < EB) {
        int e = blockIdx.x * 256 + threadIdx.x;
        if (e < E_TOTAL) atomicAdd(&counts[load_idx(dst_v, e)], 1);
    } else {
        int idx = (blockIdx.x - EB) * 256 + threadIdx.x;
        if (idx < 320 * 128) {
            prep_one(W1, Ws1, B1, 128, 2, idx);
        } else if (idx < 320 * 128 + 320 * 64) {
            prep_one(W2, Ws2, B2, 64, 1, idx - 320 * 128);
        }
    }
}

// ---------------------------------------------------------------------------
// 3-kernel scan: per-block scan across 98 SMs, block-sum scan, add-back.
// ---------------------------------------------------------------------------
__global__ void scan1_kernel(const int* __restrict__ counts, int* __restrict__ starts,
                             int* __restrict__ bsum) {
    __shared__ int s[256];
    int base = blockIdx.x * 1024 + threadIdx.x * 4;
    int c[4], t = 0;
#pragma unroll
    for (int j = 0; j < 4; j++) {
        c[j] = (base + j < N_NODES) ? counts[base + j] : 0;
        t += c[j];
    }
    s[threadIdx.x] = t;
    __syncthreads();
#pragma unroll
    for (int off = 1; off < 256; off <<= 1) {
        int v = (threadIdx.x >= off) ? s[threadIdx.x - off] : 0;
        __syncthreads();
        s[threadIdx.x] += v;
        __syncthreads();
    }
    int run = s[threadIdx.x] - t;   // exclusive prefix for this thread
#pragma unroll
    for (int j = 0; j < 4; j++) {
        if (base + j < N_NODES) starts[base + j] = run;
        run += c[j];
    }
    if (threadIdx.x == 255) bsum[blockIdx.x] = s[255];
}

__global__ void scan2_kernel(int* __restrict__ bsum, int nb) {
    __shared__ int s[128];
    int t = threadIdx.x;
    int v = (t < nb) ? bsum[t] : 0;
    s[t] = v;
    __syncthreads();
#pragma unroll
    for (int off = 1; off < 128; off <<= 1) {
        int u = (t >= off) ? s[t - off] : 0;
        __syncthreads();
        s[t] += u;
        __syncthreads();
    }
    if (t < nb) bsum[t] = s[t] - v;   // exclusive
}

__global__ void scan3_kernel(int* __restrict__ starts, int* __restrict__ cursor,
                             const int* __restrict__ bsum) {
    int i = blockIdx.x * blockDim.x + threadIdx.x;
    if (i < N_NODES) {
        int v = starts[i] + bsum[i >> 10];
        starts[i] = v;
        cursor[i] = v;
    }
    if (i == N_NODES) starts[N_NODES] = E_TOTAL;
}

// ---------------------------------------------------------------------------
__global__ void fill_kernel(const void* __restrict__ src_v, const void* __restrict__ dst_v,
                            int* __restrict__ cursor, int* __restrict__ elist) {
    int e = blockIdx.x * blockDim.x + threadIdx.x;
    if (e >= E_TOTAL) return;
    int r = e / E_PER_REL;
    int s = load_idx(src_v, e);
    int d = load_idx(dst_v, e);
    int pos = atomicAdd(&cursor[d], 1);
    elist[pos] = s * MSG_COLS + r * 64;
}

// ---------------------------------------------------------------------------
__device__ __forceinline__ void mma16816(float* c, const uint32_t* a, uint32_t b0, uint32_t b1) {
    asm volatile("mma.sync.aligned.m16n8k16.row.col.f32.f16.f16.f32 "
                 "{%0,%1,%2,%3}, {%4,%5,%6,%7}, {%8,%9}, {%0,%1,%2,%3};"
                 : "+f"(c[0]), "+f"(c[1]), "+f"(c[2]), "+f"(c[3])
                 : "r"(a[0]), "r"(a[1]), "r"(a[2]), "r"(a[3]), "r"(b0), "r"(b1));
}
__device__ __forceinline__ void ldsm4(uint32_t* r, uint32_t addr) {
    asm volatile("ldmatrix.sync.aligned.m8n8.x4.shared.b16 {%0,%1,%2,%3}, [%4];"
                 : "=r"(r[0]), "=r"(r[1]), "=r"(r[2]), "=r"(r[3]) : "r"(addr));
}
__device__ __forceinline__ void cp16(uint32_t saddr, const void* gaddr, int srcsz) {
    asm volatile("cp.async.cg.shared.global [%0], [%1], 16, %2;"
                 :: "r"(saddr), "l"(gaddr), "r"(srcsz) : "memory");
}
__device__ __forceinline__ void cp16f(uint32_t saddr, const void* gaddr) {
    asm volatile("cp.async.cg.shared.global [%0], [%1], 16;"
                 :: "r"(saddr), "l"(gaddr) : "memory");
}

// ---------------------------------------------------------------------------
// Tensor-core GEMM, fp16 A (pre-converted). CTA = 128m x 64n; cb = blockIdx.x.
// A and B tiles staged via cp.async (global -> smem direct, zero-fill OOB).
// cb 0 -> acc[N,64]; cb 1..4 -> msg[N,256]. Staged fp16 epilogue.
// ---------------------------------------------------------------------------
#define STG_STRIDE 72   // halves per staged row (64 + 8 pad -> 144 B)

template <int CHUNKS>
__global__ void __launch_bounds__(256, 3) gemm_mma_kernel(const __half* __restrict__ A, int lda,
                                                          const __half* __restrict__ B,
                                                          __half* __restrict__ Cacc,
                                                          __half* __restrict__ Cmsg) {
    __shared__ __align__(16) char S[24576];
    __half* Ah  = (__half*)(S);             // 16 KB
    __half* Bhs = (__half*)(S + 16384);     // 8 KB
    __half* stage = (__half*)S;             // reused post-compute (18.4 KB)

    const int tid  = threadIdx.x;
    const int wid  = tid >> 5;
    const int lane = tid & 31;
    const int cb   = blockIdx.x;      // column block (0..4)
    const int m0   = blockIdx.y * 128;
    const int wm   = wid >> 1;
    const int wn   = wid & 1;

    const uint32_t ah_u = (uint32_t)__cvta_generic_to_shared(Ah);
    const uint32_t bh_u = (uint32_t)__cvta_generic_to_shared(Bhs);

    const int tq = lane >> 3;
    const int lr = lane & 7;
    const int a_lrow = lr + (tq & 1) * 8;
    const int a_gad  = (tq >> 1);
    const int b_lr   = lr + (tq >> 1) * 8;
    const int b_gad  = (tq & 1);

    float acc[2][4][4];
#pragma unroll
    for (int mt = 0; mt < 2; mt++)
#pragma unroll
        for (int j = 0; j < 4; j++)
#pragma unroll
            for (int q = 0; q < 4; q++) acc[mt][j][q] = 0.f;

    for (int ch = 0; ch < CHUNKS; ch++) {
        // ---- B tile (8 KB) via cp.async
        {
            const char* bp = (const char*)B + (size_t)(cb * CHUNKS + ch) * 8192;
            cp16f(bh_u + tid * 16, bp + tid * 16);
            cp16f(bh_u + tid * 16 + 4096, bp + tid * 16 + 4096);
        }
        // ---- A tile [128m x 64k] (16 KB) via cp.async, swizzled dst
#pragma unroll
        for (int i = 0; i < 4; i++) {
            int gran = i * 256 + tid;       // 1024 granules of 8 halves
            int m = gran >> 3;
            int g = gran & 7;
            int gr = m0 + m;
            int sz = (gr < N_NODES) ? 16 : 0;
            cp16(ah_u + swz((uint32_t)m, (uint32_t)(g * 8)),
                 &A[(size_t)gr * lda + ch * 64 + g * 8], sz);
        }
        asm volatile("cp.async.commit_group;");
        asm volatile("cp.async.wait_group 0;" ::: "memory");
        __syncthreads();

        // ---- Compute: 4 k-steps of 16
#pragma unroll
        for (int ks = 0; ks < 4; ks++) {
            uint32_t afh[2][4], bfh[2][4];
#pragma unroll
            for (int mt = 0; mt < 2; mt++) {
                int arow = wm * 32 + mt * 16 + a_lrow;
                uint32_t a_off = arow * 128u +
                                 (((uint32_t)((ks * 2 + a_gad) ^ (arow & 7))) << 4);
                ldsm4(afh[mt], ah_u + a_off);
            }
#pragma unroll
            for (int bt = 0; bt < 2; bt++) {
                int brow = wn * 32 + bt * 16 + b_lr;
                uint32_t b_off = brow * 128u +
                                 (((uint32_t)((ks * 2 + b_gad) ^ (brow & 7))) << 4);
                ldsm4(bfh[bt], bh_u + b_off);
            }
#pragma unroll
            for (int mt = 0; mt < 2; mt++)
#pragma unroll
                for (int bt = 0; bt < 2; bt++) {
                    mma16816(acc[mt][bt * 2 + 0], afh[mt], bfh[bt][0], bfh[bt][1]);
                    mma16816(acc[mt][bt * 2 + 1], afh[mt], bfh[bt][2], bfh[bt][3]);
                }
        }
        __syncthreads();
    }

    // ---- Unified fp16 epilogue: stage, then coalesced 16B stores
    const int ccol = (lane & 3) * 2;
#pragma unroll
    for (int mt = 0; mt < 2; mt++) {
        int lrow0 = wm * 32 + mt * 16 + (lane >> 2);
#pragma unroll
        for (int j = 0; j < 4; j++) {
            int lc = wn * 32 + j * 8 + ccol;
            *(__half2*)&stage[lrow0 * STG_STRIDE + lc] =
                __floats2half2_rn(acc[mt][j][0], acc[mt][j][1]);
            *(__half2*)&stage[(lrow0 + 8) * STG_STRIDE + lc] =
                __floats2half2_rn(acc[mt][j][2], acc[mt][j][3]);
        }
    }
    __syncthreads();
    __half* dstbuf = (cb == 0) ? Cacc : Cmsg;
    const int dstride = (cb == 0) ? ACC_COLS : MSG_COLS;
    const int mbase = (cb == 0) ? 0 : (cb - 1) * 64;
#pragma unroll
    for (int i = 0; i < 4; i++) {
        int chunk = i * 256 + tid;
        int row = chunk >> 3;
        int cc  = chunk & 7;
        int gr = m0 + row;
        if (gr < N_NODES) {
            uint4 v = *(const uint4*)&stage[row * STG_STRIDE + cc * 8];
            *(uint4*)&dstbuf[(size_t)gr * dstride + mbase + cc * 8] = v;
        }
    }
}

// ---------------------------------------------------------------------------
// Aggregate: total = acc[n] + sum msg[elist[i]].  4-deep unrolled gathers.
// MODE 0: write fp16 acc with relu (layer 1).
// MODE 1: write f32 out with relu+sigmoid (layer 2, fused epilogue).
// ---------------------------------------------------------------------------
__device__ __forceinline__ void add8(float4& a0, float4& a1, uint4 g) {
    __half2* h = (__half2*)&g;
    float2 f0 = __half22float2(h[0]), f1 = __half22float2(h[1]);
    float2 f2 = __half22float2(h[2]), f3 = __half22float2(h[3]);
    a0.x += f0.x; a0.y += f0.y; a0.z += f1.x; a0.w += f1.y;
    a1.x += f2.x; a1.y += f2.y; a1.z += f3.x; a1.w += f3.y;
}

template <int MODE>
__global__ void __launch_bounds__(256) agg_kernel(const int* __restrict__ starts,
                                                  const int* __restrict__ elist,
                                                  const __half* __restrict__ msg,
                                                  __half* __restrict__ acc,
                                                  float* __restrict__ out) {
    int gid = blockIdx.x * blockDim.x + threadIdx.x;
    int n   = gid >> 3;
    if (n >= N_NODES) return;
    int sub = gid & 7;

    int beg = __ldg(&starts[n]);
    int end = __ldg(&starts[n + 1]);

    __half* ap = &acc[(size_t)n * ACC_COLS + sub * 8];
    uint4 aw = *(const uint4*)ap;
    float4 a0 = make_float4(0.f, 0.f, 0.f, 0.f), a1 = a0;
    add8(a0, a1, aw);   // self-path from gemm cb0

    int i = beg;
    for (; i + 3 < end; i += 4) {
        int o0 = __ldg(&elist[i]);
        int o1 = __ldg(&elist[i + 1]);
        int o2 = __ldg(&elist[i + 2]);
        int o3 = __ldg(&elist[i + 3]);
        uint4 g0 = *(const uint4*)&msg[(size_t)o0 + sub * 8];
        uint4 g1 = *(const uint4*)&msg[(size_t)o1 + sub * 8];
        uint4 g2 = *(const uint4*)&msg[(size_t)o2 + sub * 8];
        uint4 g3 = *(const uint4*)&msg[(size_t)o3 + sub * 8];
        add8(a0, a1, g0); add8(a0, a1, g1);
        add8(a0, a1, g2); add8(a0, a1, g3);
    }
    for (; i < end; i++) {
        int o0 = __ldg(&elist[i]);
        uint4 g0 = *(const uint4*)&msg[(size_t)o0 + sub * 8];
        add8(a0, a1, g0);
    }

    a0.x = fmaxf(a0.x, 0.f); a0.y = fmaxf(a0.y, 0.f);
    a0.z = fmaxf(a0.z, 0.f); a0.w = fmaxf(a0.w, 0.f);
    a1.x = fmaxf(a1.x, 0.f); a1.y = fmaxf(a1.y, 0.f);
    a1.z = fmaxf(a1.z, 0.f); a1.w = fmaxf(a1.w, 0.f);

    if (MODE == 0) {
        __half h[8];
        h[0] = __float2half_rn(a0.x); h[1] = __float2half_rn(a0.y);
        h[2] = __float2half_rn(a0.z); h[3] = __float2half_rn(a0.w);
        h[4] = __float2half_rn(a1.x); h[5] = __float2half_rn(a1.y);
        h[6] = __float2half_rn(a1.z); h[7] = __float2half_rn(a1.w);
        *(uint4*)ap = *(const uint4*)h;
    } else {
        float r[8] = {a0.x, a0.y, a0.z, a0.w, a1.x, a1.y, a1.z, a1.w};
#pragma unroll
        for (int j = 0; j < 8; j++)
            r[j] = 1.f / (1.f + __expf(-r[j]));
        float4* op = (float4*)&out[(size_t)n * ACC_COLS + sub * 8];
        op[0] = make_float4(r[0], r[1], r[2], r[3]);
        op[1] = make_float4(r[4], r[5], r[6], r[7]);
    }
}

// ---------------------------------------------------------------------------
extern "C" void kernel_launch(void* const* d_in, const int* in_sizes, int n_in,
                              void* d_out, int out_size) {
    const float* node_emb = (const float*)d_in[0];
    const void*  src      = d_in[1];
    const void*  dst      = d_in[2];
    const float* W1       = (const float*)d_in[3];
    const float* Wself1   = (const float*)d_in[4];
    const float* W2       = (const float*)d_in[5];
    const float* Wself2   = (const float*)d_in[6];
    float*       out      = (float*)d_out;

    __half *emb, *acc1, *acc2, *msg1, *msg2, *B1, *B2;
    int *counts, *starts, *cursor, *bsum, *elist;
    cudaGetSymbolAddress((void**)&emb, g_emb);
    cudaGetSymbolAddress((void**)&acc1, g_acc1);
    cudaGetSymbolAddress((void**)&acc2, g_acc2);
    cudaGetSymbolAddress((void**)&msg1, g_msg1);
    cudaGetSymbolAddress((void**)&msg2, g_msg2);
    cudaGetSymbolAddress((void**)&B1, g_B1);
    cudaGetSymbolAddress((void**)&B2, g_B2);
    cudaGetSymbolAddress((void**)&counts, g_counts);
    cudaGetSymbolAddress((void**)&starts, g_starts);
    cudaGetSymbolAddress((void**)&cursor, g_cursor);
    cudaGetSymbolAddress((void**)&bsum, g_bsum);
    cudaGetSymbolAddress((void**)&elist, g_elist);

    const int nb1024 = (N_NODES + 1023) / 1024;   // 98

    // ---- edge-list build + emb convert (6 launches)
    zero_sniff_conv_kernel<<<ZB + CONVB, 256>>>((const unsigned int*)src, counts,
                                                node_emb, emb);
    count_prep_kernel<<<EB + PREPB, 256>>>(dst, counts, W1, Wself1, W2, Wself2, B1, B2);
    scan1_kernel<<<nb1024, 256>>>(counts, starts, bsum);
    scan2_kernel<<<1, 128>>>(bsum, nb1024);
    scan3_kernel<<<(N_NODES + 256) / 256, 256>>>(starts, cursor, bsum);
    fill_kernel<<<EB, 256>>>(src, dst, cursor, elist);

    const int mblocks = (N_NODES + 127) / 128;             // 782
    const int ablocks = (N_NODES * 8 + 255) / 256;         // 3125

    // Layer 1: acc1/msg1 = emb(fp16) @ Wc1; aggregate + relu into acc1 (fp16)
    gemm_mma_kernel<2><<<dim3(5, mblocks), 256>>>(emb, 128, B1, acc1, msg1);
    agg_kernel<0><<<ablocks, 256>>>(starts, elist, msg1, acc1, nullptr);

    // Layer 2: acc2/msg2 = acc1(fp16) @ Wc2; aggregate + relu + sigmoid -> out
    gemm_mma_kernel<1><<<dim3(5, mblocks), 256>>>(acc1, ACC_COLS, B2, acc2, msg2);
    agg_kernel<1><<<ablocks, 256>>>(starts, elist, msg2, acc2, out);
}

// round 16
// speedup vs baseline: 2.2410x; 1.0055x over previous
#include <cuda_runtime.h>
#include <cuda_fp16.h>
#include <cstdint>

#define N_NODES   100000
#define E_PER_REL 150000
#define R_REL     4
#define E_TOTAL   (E_PER_REL * R_REL)
#define MSG_COLS  256
#define ACC_COLS  64

// ---------------------------------------------------------------------------
// Device globals (no runtime allocation allowed)
// ---------------------------------------------------------------------------
__device__ __align__(128) __half g_emb[(size_t)N_NODES * 128];        // 25.6 MB (fp16 node_emb)
__device__ __align__(128) __half g_acc1[(size_t)N_NODES * ACC_COLS];  // 12.8 MB
__device__ __align__(128) __half g_acc2[(size_t)N_NODES * ACC_COLS];  // 12.8 MB
__device__ __align__(128) __half g_msg1[(size_t)N_NODES * MSG_COLS];  // 51.2 MB
__device__ __align__(128) __half g_msg2[(size_t)N_NODES * MSG_COLS];  // 51.2 MB
// Pre-swizzled fp16 weight tiles: [cb*CHUNKS+ch] tiles of 64n x 64k (8192 B)
__device__ __align__(256) __half g_B1[5 * 2 * 64 * 64];
__device__ __align__(256) __half g_B2[5 * 1 * 64 * 64];
// dst-sorted edge structures (rebuilt every launch; deterministic work)
__device__ int g_counts[N_NODES];
__device__ int g_starts[N_NODES + 1];
__device__ int g_cursor[N_NODES];
__device__ int g_bsum[128];
__device__ int g_elist[E_TOTAL];    // src msg half-offsets, grouped by dst
__device__ int g_idx_is64;

// XOR swizzle on 16B granules within a 128B row: byte offset for (row, k)
__device__ __forceinline__ uint32_t swz(uint32_t row, uint32_t k) {
    uint32_t g = k >> 3;
    return row * 128u + (((g ^ (row & 7u)) << 4) | ((k & 7u) << 1));
}

__device__ __forceinline__ int load_idx(const void* v, int e) {
    return g_idx_is64 ? (int)((const long long*)v)[e] : ((const int*)v)[e];
}

// ---------------------------------------------------------------------------
// Fused: zero counts + dtype sniff (blocks [0, ZB)) and node_emb f32->fp16
// convert (blocks [ZB, ZB+CONVB)).
// ---------------------------------------------------------------------------
#define ZB ((N_NODES + 255) / 256)           // 391
#define CONVB ((N_NODES * 16 + 255) / 256)   // 6250  (N*128 elems / 8 per thread)

__global__ void zero_sniff_conv_kernel(const unsigned int* __restrict__ idx,
                                       int* __restrict__ counts,
                                       const float* __restrict__ emb_f32,
                                       __half* __restrict__ emb_f16) {
    if (blockIdx.x < ZB) {
        int i = blockIdx.x * 256 + threadIdx.x;
        if (i < N_NODES) counts[i] = 0;
        if (blockIdx.x == 0) {
            __shared__ int nz;
            if (threadIdx.x == 0) nz = 0;
            __syncthreads();
            for (int j = threadIdx.x; j < 4096; j += blockDim.x)
                if (idx[2 * j + 1] != 0u) nz = 1;
            __syncthreads();
            if (threadIdx.x == 0) g_idx_is64 = (nz == 0) ? 1 : 0;
        }
    } else {
        int t = (blockIdx.x - ZB) * 256 + threadIdx.x;   // granule of 8 elems
        if (t < N_NODES * 16) {
            const float* ap = &emb_f32[(size_t)t * 8];
            float4 v0 = *(const float4*)ap;
            float4 v1 = *(const float4*)(ap + 4);
            __half h[8];
            h[0] = __float2half_rn(v0.x); h[1] = __float2half_rn(v0.y);
            h[2] = __float2half_rn(v0.z); h[3] = __float2half_rn(v0.w);
            h[4] = __float2half_rn(v1.x); h[5] = __float2half_rn(v1.y);
            h[6] = __float2half_rn(v1.z); h[7] = __float2half_rn(v1.w);
            *(uint4*)&emb_f16[(size_t)t * 8] = *(const uint4*)h;
        }
    }
}

// ---------------------------------------------------------------------------
// Weight prep helper: combined signed weights -> swizzled fp16 tiles.
// Column c: 0..63 = Wself; 64.. = sign_r * Wrel (r=3 negated).
// ---------------------------------------------------------------------------
__device__ __forceinline__ void prep_one(const float* Wrel, const float* Wself,
                                         __half* B, int din, int chunks, int i) {
    int c = i / din;
    int d = i - c * din;
    float v;
    if (c < 64) {
        v = Wself[d * 64 + c];
    } else {
        int r = (c - 64) >> 6;
        int o = (c - 64) & 63;
        v = Wrel[((size_t)r * din + d) * 64 + o];
        if (r == 3) v = -v;   // SUBTRACT_REL = 3
    }
    int cb = c >> 6, n = c & 63;
    int ch = d >> 6, k = d & 63;
    size_t tile = (size_t)(cb * chunks + ch) * 8192;   // bytes
    *(__half*)((char*)B + tile + swz((uint32_t)n, (uint32_t)k)) = __float2half_rn(v);
}

// ---------------------------------------------------------------------------
// Fused: in-degree count, 4 edges/thread, MLP=4 (blocks [0, EB4)) + weight
// prep (blocks [EB4, EB4+PREPB)).
// ---------------------------------------------------------------------------
#define EB4 ((E_TOTAL / 4 + 255) / 256)              // 586
#define PREPB ((320 * 128 + 320 * 64 + 255) / 256)   // 240

__global__ void count_prep_kernel(const void* __restrict__ dst_v,
                                  int* __restrict__ counts,
                                  const float* __restrict__ W1, const float* __restrict__ Ws1,
                                  const float* __restrict__ W2, const float* __restrict__ Ws2,
                                  __half* __restrict__ B1, __half* __restrict__ B2) {
    if (blockIdx.x < EB4) {
        int base = (blockIdx.x * 256 + threadIdx.x) * 4;   // E_TOTAL % 4 == 0
        if (base < E_TOTAL) {
            int d0 = load_idx(dst_v, base + 0);
            int d1 = load_idx(dst_v, base + 1);
            int d2 = load_idx(dst_v, base + 2);
            int d3 = load_idx(dst_v, base + 3);
            atomicAdd(&counts[d0], 1);
            atomicAdd(&counts[d1], 1);
            atomicAdd(&counts[d2], 1);
            atomicAdd(&counts[d3], 1);
        }
    } else {
        int idx = (blockIdx.x - EB4) * 256 + threadIdx.x;
        if (idx < 320 * 128) {
            prep_one(W1, Ws1, B1, 128, 2, idx);
        } else if (idx < 320 * 128 + 320 * 64) {
            prep_one(W2, Ws2, B2, 64, 1, idx - 320 * 128);
        }
    }
}

// ---------------------------------------------------------------------------
// scan1: per-1024-node block scan (98 blocks); writes block totals to bsum.
// scan3m: add-back with the bsum prefix computed IN-BLOCK (replaces scan2).
// ---------------------------------------------------------------------------
__global__ void scan1_kernel(const int* __restrict__ counts, int* __restrict__ starts,
                             int* __restrict__ bsum) {
    __shared__ int s[256];
    int base = blockIdx.x * 1024 + threadIdx.x * 4;
    int c[4], t = 0;
#pragma unroll
    for (int j = 0; j < 4; j++) {
        c[j] = (base + j < N_NODES) ? counts[base + j] : 0;
        t += c[j];
    }
    s[threadIdx.x] = t;
    __syncthreads();
#pragma unroll
    for (int off = 1; off < 256; off <<= 1) {
        int v = (threadIdx.x >= off) ? s[threadIdx.x - off] : 0;
        __syncthreads();
        s[threadIdx.x] += v;
        __syncthreads();
    }
    int run = s[threadIdx.x] - t;   // exclusive prefix for this thread
#pragma unroll
    for (int j = 0; j < 4; j++) {
        if (base + j < N_NODES) starts[base + j] = run;
        run += c[j];
    }
    if (threadIdx.x == 255) bsum[blockIdx.x] = s[255];
}

__global__ void scan3m_kernel(int* __restrict__ starts, int* __restrict__ cursor,
                              const int* __restrict__ bsum) {
    __shared__ int s[256];
    int t = threadIdx.x;
    int seg = blockIdx.x >> 2;          // 1024-node segment of this block
    s[t] = (t < seg) ? __ldg(&bsum[t]) : 0;   // seg <= 97 < 256
    __syncthreads();
#pragma unroll
    for (int off = 128; off > 0; off >>= 1) {
        if (t < off) s[t] += s[t + off];
        __syncthreads();
    }
    int boff = s[0];                    // sum of bsum[0..seg-1] (exclusive)
    int i = blockIdx.x * 256 + t;
    if (i < N_NODES) {
        int v = starts[i] + boff;
        starts[i] = v;
        cursor[i] = v;
    }
    if (i == N_NODES) starts[N_NODES] = E_TOTAL;
}

// ---------------------------------------------------------------------------
// fill: 4 edges/thread; all 8 idx loads issued before atomics (MLP=4).
// ---------------------------------------------------------------------------
__global__ void fill_kernel(const void* __restrict__ src_v, const void* __restrict__ dst_v,
                            int* __restrict__ cursor, int* __restrict__ elist) {
    int base = (blockIdx.x * blockDim.x + threadIdx.x) * 4;
    if (base >= E_TOTAL) return;
    int s0 = load_idx(src_v, base + 0);
    int s1 = load_idx(src_v, base + 1);
    int s2 = load_idx(src_v, base + 2);
    int s3 = load_idx(src_v, base + 3);
    int d0 = load_idx(dst_v, base + 0);
    int d1 = load_idx(dst_v, base + 1);
    int d2 = load_idx(dst_v, base + 2);
    int d3 = load_idx(dst_v, base + 3);
    int r0 = (base + 0) / E_PER_REL;
    int r1 = (base + 1) / E_PER_REL;
    int r2 = (base + 2) / E_PER_REL;
    int r3 = (base + 3) / E_PER_REL;
    int p0 = atomicAdd(&cursor[d0], 1);
    int p1 = atomicAdd(&cursor[d1], 1);
    int p2 = atomicAdd(&cursor[d2], 1);
    int p3 = atomicAdd(&cursor[d3], 1);
    elist[p0] = s0 * MSG_COLS + r0 * 64;
    elist[p1] = s1 * MSG_COLS + r1 * 64;
    elist[p2] = s2 * MSG_COLS + r2 * 64;
    elist[p3] = s3 * MSG_COLS + r3 * 64;
}

// ---------------------------------------------------------------------------
__device__ __forceinline__ void mma16816(float* c, const uint32_t* a, uint32_t b0, uint32_t b1) {
    asm volatile("mma.sync.aligned.m16n8k16.row.col.f32.f16.f16.f32 "
                 "{%0,%1,%2,%3}, {%4,%5,%6,%7}, {%8,%9}, {%0,%1,%2,%3};"
                 : "+f"(c[0]), "+f"(c[1]), "+f"(c[2]), "+f"(c[3])
                 : "r"(a[0]), "r"(a[1]), "r"(a[2]), "r"(a[3]), "r"(b0), "r"(b1));
}
__device__ __forceinline__ void ldsm4(uint32_t* r, uint32_t addr) {
    asm volatile("ldmatrix.sync.aligned.m8n8.x4.shared.b16 {%0,%1,%2,%3}, [%4];"
                 : "=r"(r[0]), "=r"(r[1]), "=r"(r[2]), "=r"(r[3]) : "r"(addr));
}
__device__ __forceinline__ void cp16(uint32_t saddr, const void* gaddr, int srcsz) {
    asm volatile("cp.async.cg.shared.global [%0], [%1], 16, %2;"
                 :: "r"(saddr), "l"(gaddr), "r"(srcsz) : "memory");
}
__device__ __forceinline__ void cp16f(uint32_t saddr, const void* gaddr) {
    asm volatile("cp.async.cg.shared.global [%0], [%1], 16;"
                 :: "r"(saddr), "l"(gaddr) : "memory");
}

// ---------------------------------------------------------------------------
// Tensor-core GEMM, fp16 A (pre-converted). CTA = 128m x 64n; cb = blockIdx.x.
// A and B tiles staged via cp.async (global -> smem direct, zero-fill OOB).
// cb 0 -> acc[N,64]; cb 1..4 -> msg[N,256]. Staged fp16 epilogue.
// ---------------------------------------------------------------------------
#define STG_STRIDE 72   // halves per staged row (64 + 8 pad -> 144 B)

template <int CHUNKS>
__global__ void __launch_bounds__(256, 3) gemm_mma_kernel(const __half* __restrict__ A, int lda,
                                                          const __half* __restrict__ B,
                                                          __half* __restrict__ Cacc,
                                                          __half* __restrict__ Cmsg) {
    __shared__ __align__(16) char S[24576];
    __half* Ah  = (__half*)(S);             // 16 KB
    __half* Bhs = (__half*)(S + 16384);     // 8 KB
    __half* stage = (__half*)S;             // reused post-compute (18.4 KB)

    const int tid  = threadIdx.x;
    const int wid  = tid >> 5;
    const int lane = tid & 31;
    const int cb   = blockIdx.x;      // column block (0..4)
    const int m0   = blockIdx.y * 128;
    const int wm   = wid >> 1;
    const int wn   = wid & 1;

    const uint32_t ah_u = (uint32_t)__cvta_generic_to_shared(Ah);
    const uint32_t bh_u = (uint32_t)__cvta_generic_to_shared(Bhs);

    const int tq = lane >> 3;
    const int lr = lane & 7;
    const int a_lrow = lr + (tq & 1) * 8;
    const int a_gad  = (tq >> 1);
    const int b_lr   = lr + (tq >> 1) * 8;
    const int b_gad  = (tq & 1);

    float acc[2][4][4];
#pragma unroll
    for (int mt = 0; mt < 2; mt++)
#pragma unroll
        for (int j = 0; j < 4; j++)
#pragma unroll
            for (int q = 0; q < 4; q++) acc[mt][j][q] = 0.f;

    for (int ch = 0; ch < CHUNKS; ch++) {
        // ---- B tile (8 KB) via cp.async
        {
            const char* bp = (const char*)B + (size_t)(cb * CHUNKS + ch) * 8192;
            cp16f(bh_u + tid * 16, bp + tid * 16);
            cp16f(bh_u + tid * 16 + 4096, bp + tid * 16 + 4096);
        }
        // ---- A tile [128m x 64k] (16 KB) via cp.async, swizzled dst
#pragma unroll
        for (int i = 0; i < 4; i++) {
            int gran = i * 256 + tid;       // 1024 granules of 8 halves
            int m = gran >> 3;
            int g = gran & 7;
            int gr = m0 + m;
            int sz = (gr < N_NODES) ? 16 : 0;
            cp16(ah_u + swz((uint32_t)m, (uint32_t)(g * 8)),
                 &A[(size_t)gr * lda + ch * 64 + g * 8], sz);
        }
        asm volatile("cp.async.commit_group;");
        asm volatile("cp.async.wait_group 0;" ::: "memory");
        __syncthreads();

        // ---- Compute: 4 k-steps of 16
#pragma unroll
        for (int ks = 0; ks < 4; ks++) {
            uint32_t afh[2][4], bfh[2][4];
#pragma unroll
            for (int mt = 0; mt < 2; mt++) {
                int arow = wm * 32 + mt * 16 + a_lrow;
                uint32_t a_off = arow * 128u +
                                 (((uint32_t)((ks * 2 + a_gad) ^ (arow & 7))) << 4);
                ldsm4(afh[mt], ah_u + a_off);
            }
#pragma unroll
            for (int bt = 0; bt < 2; bt++) {
                int brow = wn * 32 + bt * 16 + b_lr;
                uint32_t b_off = brow * 128u +
                                 (((uint32_t)((ks * 2 + b_gad) ^ (brow & 7))) << 4);
                ldsm4(bfh[bt], bh_u + b_off);
            }
#pragma unroll
            for (int mt = 0; mt < 2; mt++)
#pragma unroll
                for (int bt = 0; bt < 2; bt++) {
                    mma16816(acc[mt][bt * 2 + 0], afh[mt], bfh[bt][0], bfh[bt][1]);
                    mma16816(acc[mt][bt * 2 + 1], afh[mt], bfh[bt][2], bfh[bt][3]);
                }
        }
        __syncthreads();
    }

    // ---- Unified fp16 epilogue: stage, then coalesced 16B stores
    const int ccol = (lane & 3) * 2;
#pragma unroll
    for (int mt = 0; mt < 2; mt++) {
        int lrow0 = wm * 32 + mt * 16 + (lane >> 2);
#pragma unroll
        for (int j = 0; j < 4; j++) {
            int lc = wn * 32 + j * 8 + ccol;
            *(__half2*)&stage[lrow0 * STG_STRIDE + lc] =
                __floats2half2_rn(acc[mt][j][0], acc[mt][j][1]);
            *(__half2*)&stage[(lrow0 + 8) * STG_STRIDE + lc] =
                __floats2half2_rn(acc[mt][j][2], acc[mt][j][3]);
        }
    }
    __syncthreads();
    __half* dstbuf = (cb == 0) ? Cacc : Cmsg;
    const int dstride = (cb == 0) ? ACC_COLS : MSG_COLS;
    const int mbase = (cb == 0) ? 0 : (cb - 1) * 64;
#pragma unroll
    for (int i = 0; i < 4; i++) {
        int chunk = i * 256 + tid;
        int row = chunk >> 3;
        int cc  = chunk & 7;
        int gr = m0 + row;
        if (gr < N_NODES) {
            uint4 v = *(const uint4*)&stage[row * STG_STRIDE + cc * 8];
            *(uint4*)&dstbuf[(size_t)gr * dstride + mbase + cc * 8] = v;
        }
    }
}

// ---------------------------------------------------------------------------
// Aggregate: total = acc[n] + sum msg[elist[i]].  4-deep unrolled gathers.
// MODE 0: write fp16 acc with relu (layer 1).
// MODE 1: write f32 out with relu+sigmoid (layer 2, fused epilogue).
// ---------------------------------------------------------------------------
__device__ __forceinline__ void add8(float4& a0, float4& a1, uint4 g) {
    __half2* h = (__half2*)&g;
    float2 f0 = __half22float2(h[0]), f1 = __half22float2(h[1]);
    float2 f2 = __half22float2(h[2]), f3 = __half22float2(h[3]);
    a0.x += f0.x; a0.y += f0.y; a0.z += f1.x; a0.w += f1.y;
    a1.x += f2.x; a1.y += f2.y; a1.z += f3.x; a1.w += f3.y;
}

template <int MODE>
__global__ void __launch_bounds__(256) agg_kernel(const int* __restrict__ starts,
                                                  const int* __restrict__ elist,
                                                  const __half* __restrict__ msg,
                                                  __half* __restrict__ acc,
                                                  float* __restrict__ out) {
    int gid = blockIdx.x * blockDim.x + threadIdx.x;
    int n   = gid >> 3;
    if (n >= N_NODES) return;
    int sub = gid & 7;

    int beg = __ldg(&starts[n]);
    int end = __ldg(&starts[n + 1]);

    __half* ap = &acc[(size_t)n * ACC_COLS + sub * 8];
    uint4 aw = *(const uint4*)ap;
    float4 a0 = make_float4(0.f, 0.f, 0.f, 0.f), a1 = a0;
    add8(a0, a1, aw);   // self-path from gemm cb0

    int i = beg;
    for (; i + 3 < end; i += 4) {
        int o0 = __ldg(&elist[i]);
        int o1 = __ldg(&elist[i + 1]);
        int o2 = __ldg(&elist[i + 2]);
        int o3 = __ldg(&elist[i + 3]);
        uint4 g0 = *(const uint4*)&msg[(size_t)o0 + sub * 8];
        uint4 g1 = *(const uint4*)&msg[(size_t)o1 + sub * 8];
        uint4 g2 = *(const uint4*)&msg[(size_t)o2 + sub * 8];
        uint4 g3 = *(const uint4*)&msg[(size_t)o3 + sub * 8];
        add8(a0, a1, g0); add8(a0, a1, g1);
        add8(a0, a1, g2); add8(a0, a1, g3);
    }
    for (; i < end; i++) {
        int o0 = __ldg(&elist[i]);
        uint4 g0 = *(const uint4*)&msg[(size_t)o0 + sub * 8];
        add8(a0, a1, g0);
    }

    a0.x = fmaxf(a0.x, 0.f); a0.y = fmaxf(a0.y, 0.f);
    a0.z = fmaxf(a0.z, 0.f); a0.w = fmaxf(a0.w, 0.f);
    a1.x = fmaxf(a1.x, 0.f); a1.y = fmaxf(a1.y, 0.f);
    a1.z = fmaxf(a1.z, 0.f); a1.w = fmaxf(a1.w, 0.f);

    if (MODE == 0) {
        __half h[8];
        h[0] = __float2half_rn(a0.x); h[1] = __float2half_rn(a0.y);
        h[2] = __float2half_rn(a0.z); h[3] = __float2half_rn(a0.w);
        h[4] = __float2half_rn(a1.x); h[5] = __float2half_rn(a1.y);
        h[6] = __float2half_rn(a1.z); h[7] = __float2half_rn(a1.w);
        *(uint4*)ap = *(const uint4*)h;
    } else {
        float r[8] = {a0.x, a0.y, a0.z, a0.w, a1.x, a1.y, a1.z, a1.w};
#pragma unroll
        for (int j = 0; j < 8; j++)
            r[j] = 1.f / (1.f + __expf(-r[j]));
        float4* op = (float4*)&out[(size_t)n * ACC_COLS + sub * 8];
        op[0] = make_float4(r[0], r[1], r[2], r[3]);
        op[1] = make_float4(r[4], r[5], r[6], r[7]);
    }
}

// ---------------------------------------------------------------------------
extern "C" void kernel_launch(void* const* d_in, const int* in_sizes, int n_in,
                              void* d_out, int out_size) {
    const float* node_emb = (const float*)d_in[0];
    const void*  src      = d_in[1];
    const void*  dst      = d_in[2];
    const float* W1       = (const float*)d_in[3];
    const float* Wself1   = (const float*)d_in[4];
    const float* W2       = (const float*)d_in[5];
    const float* Wself2   = (const float*)d_in[6];
    float*       out      = (float*)d_out;

    __half *emb, *acc1, *acc2, *msg1, *msg2, *B1, *B2;
    int *counts, *starts, *cursor, *bsum, *elist;
    cudaGetSymbolAddress((void**)&emb, g_emb);
    cudaGetSymbolAddress((void**)&acc1, g_acc1);
    cudaGetSymbolAddress((void**)&acc2, g_acc2);
    cudaGetSymbolAddress((void**)&msg1, g_msg1);
    cudaGetSymbolAddress((void**)&msg2, g_msg2);
    cudaGetSymbolAddress((void**)&B1, g_B1);
    cudaGetSymbolAddress((void**)&B2, g_B2);
    cudaGetSymbolAddress((void**)&counts, g_counts);
    cudaGetSymbolAddress((void**)&starts, g_starts);
    cudaGetSymbolAddress((void**)&cursor, g_cursor);
    cudaGetSymbolAddress((void**)&bsum, g_bsum);
    cudaGetSymbolAddress((void**)&elist, g_elist);

    const int nb1024 = (N_NODES + 1023) / 1024;   // 98

    // ---- edge-list build + emb convert (5 launches)
    zero_sniff_conv_kernel<<<ZB + CONVB, 256>>>((const unsigned int*)src, counts,
                                                node_emb, emb);
    count_prep_kernel<<<EB4 + PREPB, 256>>>(dst, counts, W1, Wself1, W2, Wself2, B1, B2);
    scan1_kernel<<<nb1024, 256>>>(counts, starts, bsum);
    scan3m_kernel<<<(N_NODES + 256) / 256, 256>>>(starts, cursor, bsum);
    fill_kernel<<<(E_TOTAL / 4 + 255) / 256, 256>>>(src, dst, cursor, elist);

    const int mblocks = (N_NODES + 127) / 128;             // 782
    const int ablocks = (N_NODES * 8 + 255) / 256;         // 3125

    // Layer 1: acc1/msg1 = emb(fp16) @ Wc1; aggregate + relu into acc1 (fp16)
    gemm_mma_kernel<2><<<dim3(5, mblocks), 256>>>(emb, 128, B1, acc1, msg1);
    agg_kernel<0><<<ablocks, 256>>>(starts, elist, msg1, acc1, nullptr);

    // Layer 2: acc2/msg2 = acc1(fp16) @ Wc2; aggregate + relu + sigmoid -> out
    gemm_mma_kernel<1><<<dim3(5, mblocks), 256>>>(acc1, ACC_COLS, B2, acc2, msg2);
    agg_kernel<1><<<ablocks, 256>>>(starts, elist, msg2, acc2, out);
}

// round 17
// speedup vs baseline: 2.2572x; 1.0072x over previous
#include <cuda_runtime.h>
#include <cuda_fp16.h>
#include <cstdint>

#define N_NODES   100000
#define E_PER_REL 150000
#define R_REL     4
#define E_TOTAL   (E_PER_REL * R_REL)
#define MSG_COLS  256
#define ACC_COLS  64

// ---------------------------------------------------------------------------
// Device globals (no runtime allocation allowed)
// ---------------------------------------------------------------------------
__device__ __align__(128) __half g_emb[(size_t)N_NODES * 128];        // 25.6 MB (fp16 node_emb)
__device__ __align__(128) __half g_acc1[(size_t)N_NODES * ACC_COLS];  // 12.8 MB
__device__ __align__(128) __half g_acc2[(size_t)N_NODES * ACC_COLS];  // 12.8 MB
__device__ __align__(128) __half g_msg1[(size_t)N_NODES * MSG_COLS];  // 51.2 MB
__device__ __align__(128) __half g_msg2[(size_t)N_NODES * MSG_COLS];  // 51.2 MB
// Pre-swizzled fp16 weight tiles: [cb*CHUNKS+ch] tiles of 64n x 64k (8192 B)
__device__ __align__(256) __half g_B1[5 * 2 * 64 * 64];
__device__ __align__(256) __half g_B2[5 * 1 * 64 * 64];
// dst-sorted edge structures (rebuilt every launch; deterministic work)
__device__ int g_counts[N_NODES];
__device__ int g_starts[N_NODES + 1];
__device__ int g_cursor[N_NODES];
__device__ int g_bsum[128];
__device__ int g_elist[E_TOTAL];    // src msg half-offsets, grouped by dst
__device__ int g_idx_is64;

// XOR swizzle on 16B granules within a 128B row: byte offset for (row, k)
__device__ __forceinline__ uint32_t swz(uint32_t row, uint32_t k) {
    uint32_t g = k >> 3;
    return row * 128u + (((g ^ (row & 7u)) << 4) | ((k & 7u) << 1));
}

__device__ __forceinline__ int load_idx(const void* v, int e) {
    return g_idx_is64 ? (int)((const long long*)v)[e] : ((const int*)v)[e];
}

// ---------------------------------------------------------------------------
// BRANCH B kernel 1: zero counts + dtype sniff (block 0).
// ---------------------------------------------------------------------------
#define ZB ((N_NODES + 255) / 256)           // 391

__global__ void zero_sniff_kernel(const unsigned int* __restrict__ idx,
                                  int* __restrict__ counts) {
    int i = blockIdx.x * 256 + threadIdx.x;
    if (i < N_NODES) counts[i] = 0;
    if (blockIdx.x == 0) {
        __shared__ int nz;
        if (threadIdx.x == 0) nz = 0;
        __syncthreads();
        for (int j = threadIdx.x; j < 4096; j += blockDim.x)
            if (idx[2 * j + 1] != 0u) nz = 1;
        __syncthreads();
        if (threadIdx.x == 0) g_idx_is64 = (nz == 0) ? 1 : 0;
    }
}

// ---------------------------------------------------------------------------
// BRANCH B kernel 2: in-degree count, 4 edges/thread (MLP=4).
// ---------------------------------------------------------------------------
#define EB4 ((E_TOTAL / 4 + 255) / 256)      // 586

__global__ void count_kernel(const void* __restrict__ dst_v, int* __restrict__ counts) {
    int base = (blockIdx.x * 256 + threadIdx.x) * 4;   // E_TOTAL % 4 == 0
    if (base >= E_TOTAL) return;
    int d0 = load_idx(dst_v, base + 0);
    int d1 = load_idx(dst_v, base + 1);
    int d2 = load_idx(dst_v, base + 2);
    int d3 = load_idx(dst_v, base + 3);
    atomicAdd(&counts[d0], 1);
    atomicAdd(&counts[d1], 1);
    atomicAdd(&counts[d2], 1);
    atomicAdd(&counts[d3], 1);
}

// ---------------------------------------------------------------------------
// BRANCH B kernels 3-4: scan1 (per-1024-node block scan, 98 blocks) then
// scan3m (add-back with bsum prefix reduced in-block).
// ---------------------------------------------------------------------------
__global__ void scan1_kernel(const int* __restrict__ counts, int* __restrict__ starts,
                             int* __restrict__ bsum) {
    __shared__ int s[256];
    int base = blockIdx.x * 1024 + threadIdx.x * 4;
    int c[4], t = 0;
#pragma unroll
    for (int j = 0; j < 4; j++) {
        c[j] = (base + j < N_NODES) ? counts[base + j] : 0;
        t += c[j];
    }
    s[threadIdx.x] = t;
    __syncthreads();
#pragma unroll
    for (int off = 1; off < 256; off <<= 1) {
        int v = (threadIdx.x >= off) ? s[threadIdx.x - off] : 0;
        __syncthreads();
        s[threadIdx.x] += v;
        __syncthreads();
    }
    int run = s[threadIdx.x] - t;   // exclusive prefix for this thread
#pragma unroll
    for (int j = 0; j < 4; j++) {
        if (base + j < N_NODES) starts[base + j] = run;
        run += c[j];
    }
    if (threadIdx.x == 255) bsum[blockIdx.x] = s[255];
}

__global__ void scan3m_kernel(int* __restrict__ starts, int* __restrict__ cursor,
                              const int* __restrict__ bsum) {
    __shared__ int s[256];
    int t = threadIdx.x;
    int seg = blockIdx.x >> 2;          // 1024-node segment of this block
    s[t] = (t < seg) ? __ldg(&bsum[t]) : 0;   // seg <= 97 < 256
    __syncthreads();
#pragma unroll
    for (int off = 128; off > 0; off >>= 1) {
        if (t < off) s[t] += s[t + off];
        __syncthreads();
    }
    int boff = s[0];                    // sum of bsum[0..seg-1] (exclusive)
    int i = blockIdx.x * 256 + t;
    if (i < N_NODES) {
        int v = starts[i] + boff;
        starts[i] = v;
        cursor[i] = v;
    }
    if (i == N_NODES) starts[N_NODES] = E_TOTAL;
}

// ---------------------------------------------------------------------------
// BRANCH B kernel 5: fill, 4 edges/thread, loads batched before atomics.
// ---------------------------------------------------------------------------
__global__ void fill_kernel(const void* __restrict__ src_v, const void* __restrict__ dst_v,
                            int* __restrict__ cursor, int* __restrict__ elist) {
    int base = (blockIdx.x * blockDim.x + threadIdx.x) * 4;
    if (base >= E_TOTAL) return;
    int s0 = load_idx(src_v, base + 0);
    int s1 = load_idx(src_v, base + 1);
    int s2 = load_idx(src_v, base + 2);
    int s3 = load_idx(src_v, base + 3);
    int d0 = load_idx(dst_v, base + 0);
    int d1 = load_idx(dst_v, base + 1);
    int d2 = load_idx(dst_v, base + 2);
    int d3 = load_idx(dst_v, base + 3);
    int r0 = (base + 0) / E_PER_REL;
    int r1 = (base + 1) / E_PER_REL;
    int r2 = (base + 2) / E_PER_REL;
    int r3 = (base + 3) / E_PER_REL;
    int p0 = atomicAdd(&cursor[d0], 1);
    int p1 = atomicAdd(&cursor[d1], 1);
    int p2 = atomicAdd(&cursor[d2], 1);
    int p3 = atomicAdd(&cursor[d3], 1);
    elist[p0] = s0 * MSG_COLS + r0 * 64;
    elist[p1] = s1 * MSG_COLS + r1 * 64;
    elist[p2] = s2 * MSG_COLS + r2 * 64;
    elist[p3] = s3 * MSG_COLS + r3 * 64;
}

// ---------------------------------------------------------------------------
// BRANCH A kernel 1: node_emb f32->fp16 convert + weight prep (block ranges).
// ---------------------------------------------------------------------------
__device__ __forceinline__ void prep_one(const float* Wrel, const float* Wself,
                                         __half* B, int din, int chunks, int i) {
    int c = i / din;
    int d = i - c * din;
    float v;
    if (c < 64) {
        v = Wself[d * 64 + c];
    } else {
        int r = (c - 64) >> 6;
        int o = (c - 64) & 63;
        v = Wrel[((size_t)r * din + d) * 64 + o];
        if (r == 3) v = -v;   // SUBTRACT_REL = 3
    }
    int cb = c >> 6, n = c & 63;
    int ch = d >> 6, k = d & 63;
    size_t tile = (size_t)(cb * chunks + ch) * 8192;   // bytes
    *(__half*)((char*)B + tile + swz((uint32_t)n, (uint32_t)k)) = __float2half_rn(v);
}

#define CONVB ((N_NODES * 16 + 255) / 256)           // 6250
#define PREPB ((320 * 128 + 320 * 64 + 255) / 256)   // 240

__global__ void conv_prep_kernel(const float* __restrict__ emb_f32,
                                 __half* __restrict__ emb_f16,
                                 const float* __restrict__ W1, const float* __restrict__ Ws1,
                                 const float* __restrict__ W2, const float* __restrict__ Ws2,
                                 __half* __restrict__ B1, __half* __restrict__ B2) {
    if (blockIdx.x < CONVB) {
        int t = blockIdx.x * 256 + threadIdx.x;   // granule of 8 elems
        if (t < N_NODES * 16) {
            const float* ap = &emb_f32[(size_t)t * 8];
            float4 v0 = *(const float4*)ap;
            float4 v1 = *(const float4*)(ap + 4);
            __half h[8];
            h[0] = __float2half_rn(v0.x); h[1] = __float2half_rn(v0.y);
            h[2] = __float2half_rn(v0.z); h[3] = __float2half_rn(v0.w);
            h[4] = __float2half_rn(v1.x); h[5] = __float2half_rn(v1.y);
            h[6] = __float2half_rn(v1.z); h[7] = __float2half_rn(v1.w);
            *(uint4*)&emb_f16[(size_t)t * 8] = *(const uint4*)h;
        }
    } else {
        int idx = (blockIdx.x - CONVB) * 256 + threadIdx.x;
        if (idx < 320 * 128) {
            prep_one(W1, Ws1, B1, 128, 2, idx);
        } else if (idx < 320 * 128 + 320 * 64) {
            prep_one(W2, Ws2, B2, 64, 1, idx - 320 * 128);
        }
    }
}

// ---------------------------------------------------------------------------
__device__ __forceinline__ void mma16816(float* c, const uint32_t* a, uint32_t b0, uint32_t b1) {
    asm volatile("mma.sync.aligned.m16n8k16.row.col.f32.f16.f16.f32 "
                 "{%0,%1,%2,%3}, {%4,%5,%6,%7}, {%8,%9}, {%0,%1,%2,%3};"
                 : "+f"(c[0]), "+f"(c[1]), "+f"(c[2]), "+f"(c[3])
                 : "r"(a[0]), "r"(a[1]), "r"(a[2]), "r"(a[3]), "r"(b0), "r"(b1));
}
__device__ __forceinline__ void ldsm4(uint32_t* r, uint32_t addr) {
    asm volatile("ldmatrix.sync.aligned.m8n8.x4.shared.b16 {%0,%1,%2,%3}, [%4];"
                 : "=r"(r[0]), "=r"(r[1]), "=r"(r[2]), "=r"(r[3]) : "r"(addr));
}
__device__ __forceinline__ void cp16(uint32_t saddr, const void* gaddr, int srcsz) {
    asm volatile("cp.async.cg.shared.global [%0], [%1], 16, %2;"
                 :: "r"(saddr), "l"(gaddr), "r"(srcsz) : "memory");
}
__device__ __forceinline__ void cp16f(uint32_t saddr, const void* gaddr) {
    asm volatile("cp.async.cg.shared.global [%0], [%1], 16;"
                 :: "r"(saddr), "l"(gaddr) : "memory");
}

// ---------------------------------------------------------------------------
// Tensor-core GEMM, fp16 A. CTA = 128m x 64n; cb = blockIdx.x (0..4).
// A and B tiles staged via cp.async. cb 0 -> acc[N,64]; cb 1..4 -> msg[N,256].
// ---------------------------------------------------------------------------
#define STG_STRIDE 72   // halves per staged row (64 + 8 pad -> 144 B)

template <int CHUNKS>
__global__ void __launch_bounds__(256, 3) gemm_mma_kernel(const __half* __restrict__ A, int lda,
                                                          const __half* __restrict__ B,
                                                          __half* __restrict__ Cacc,
                                                          __half* __restrict__ Cmsg) {
    __shared__ __align__(16) char S[24576];
    __half* Ah  = (__half*)(S);             // 16 KB
    __half* Bhs = (__half*)(S + 16384);     // 8 KB
    __half* stage = (__half*)S;             // reused post-compute (18.4 KB)

    const int tid  = threadIdx.x;
    const int wid  = tid >> 5;
    const int lane = tid & 31;
    const int cb   = blockIdx.x;      // column block (0..4)
    const int m0   = blockIdx.y * 128;
    const int wm   = wid >> 1;
    const int wn   = wid & 1;

    const uint32_t ah_u = (uint32_t)__cvta_generic_to_shared(Ah);
    const uint32_t bh_u = (uint32_t)__cvta_generic_to_shared(Bhs);

    const int tq = lane >> 3;
    const int lr = lane & 7;
    const int a_lrow = lr + (tq & 1) * 8;
    const int a_gad  = (tq >> 1);
    const int b_lr   = lr + (tq >> 1) * 8;
    const int b_gad  = (tq & 1);

    float acc[2][4][4];
#pragma unroll
    for (int mt = 0; mt < 2; mt++)
#pragma unroll
        for (int j = 0; j < 4; j++)
#pragma unroll
            for (int q = 0; q < 4; q++) acc[mt][j][q] = 0.f;

    for (int ch = 0; ch < CHUNKS; ch++) {
        // ---- B tile (8 KB) via cp.async
        {
            const char* bp = (const char*)B + (size_t)(cb * CHUNKS + ch) * 8192;
            cp16f(bh_u + tid * 16, bp + tid * 16);
            cp16f(bh_u + tid * 16 + 4096, bp + tid * 16 + 4096);
        }
        // ---- A tile [128m x 64k] (16 KB) via cp.async, swizzled dst
#pragma unroll
        for (int i = 0; i < 4; i++) {
            int gran = i * 256 + tid;       // 1024 granules of 8 halves
            int m = gran >> 3;
            int g = gran & 7;
            int gr = m0 + m;
            int sz = (gr < N_NODES) ? 16 : 0;
            cp16(ah_u + swz((uint32_t)m, (uint32_t)(g * 8)),
                 &A[(size_t)gr * lda + ch * 64 + g * 8], sz);
        }
        asm volatile("cp.async.commit_group;");
        asm volatile("cp.async.wait_group 0;" ::: "memory");
        __syncthreads();

        // ---- Compute: 4 k-steps of 16
#pragma unroll
        for (int ks = 0; ks < 4; ks++) {
            uint32_t afh[2][4], bfh[2][4];
#pragma unroll
            for (int mt = 0; mt < 2; mt++) {
                int arow = wm * 32 + mt * 16 + a_lrow;
                uint32_t a_off = arow * 128u +
                                 (((uint32_t)((ks * 2 + a_gad) ^ (arow & 7))) << 4);
                ldsm4(afh[mt], ah_u + a_off);
            }
#pragma unroll
            for (int bt = 0; bt < 2; bt++) {
                int brow = wn * 32 + bt * 16 + b_lr;
                uint32_t b_off = brow * 128u +
                                 (((uint32_t)((ks * 2 + b_gad) ^ (brow & 7))) << 4);
                ldsm4(bfh[bt], bh_u + b_off);
            }
#pragma unroll
            for (int mt = 0; mt < 2; mt++)
#pragma unroll
                for (int bt = 0; bt < 2; bt++) {
                    mma16816(acc[mt][bt * 2 + 0], afh[mt], bfh[bt][0], bfh[bt][1]);
                    mma16816(acc[mt][bt * 2 + 1], afh[mt], bfh[bt][2], bfh[bt][3]);
                }
        }
        __syncthreads();
    }

    // ---- Unified fp16 epilogue: stage, then coalesced 16B stores
    const int ccol = (lane & 3) * 2;
#pragma unroll
    for (int mt = 0; mt < 2; mt++) {
        int lrow0 = wm * 32 + mt * 16 + (lane >> 2);
#pragma unroll
        for (int j = 0; j < 4; j++) {
            int lc = wn * 32 + j * 8 + ccol;
            *(__half2*)&stage[lrow0 * STG_STRIDE + lc] =
                __floats2half2_rn(acc[mt][j][0], acc[mt][j][1]);
            *(__half2*)&stage[(lrow0 + 8) * STG_STRIDE + lc] =
                __floats2half2_rn(acc[mt][j][2], acc[mt][j][3]);
        }
    }
    __syncthreads();
    __half* dstbuf = (cb == 0) ? Cacc : Cmsg;
    const int dstride = (cb == 0) ? ACC_COLS : MSG_COLS;
    const int mbase = (cb == 0) ? 0 : (cb - 1) * 64;
#pragma unroll
    for (int i = 0; i < 4; i++) {
        int chunk = i * 256 + tid;
        int row = chunk >> 3;
        int cc  = chunk & 7;
        int gr = m0 + row;
        if (gr < N_NODES) {
            uint4 v = *(const uint4*)&stage[row * STG_STRIDE + cc * 8];
            *(uint4*)&dstbuf[(size_t)gr * dstride + mbase + cc * 8] = v;
        }
    }
}

// ---------------------------------------------------------------------------
// Aggregate: total = acc[n] + sum msg[elist[i]].  4-deep unrolled gathers.
// MODE 0: write fp16 acc with relu (layer 1).
// MODE 1: write f32 out with relu+sigmoid (layer 2, fused epilogue).
// ---------------------------------------------------------------------------
__device__ __forceinline__ void add8(float4& a0, float4& a1, uint4 g) {
    __half2* h = (__half2*)&g;
    float2 f0 = __half22float2(h[0]), f1 = __half22float2(h[1]);
    float2 f2 = __half22float2(h[2]), f3 = __half22float2(h[3]);
    a0.x += f0.x; a0.y += f0.y; a0.z += f1.x; a0.w += f1.y;
    a1.x += f2.x; a1.y += f2.y; a1.z += f3.x; a1.w += f3.y;
}

template <int MODE>
__global__ void __launch_bounds__(256) agg_kernel(const int* __restrict__ starts,
                                                  const int* __restrict__ elist,
                                                  const __half* __restrict__ msg,
                                                  __half* __restrict__ acc,
                                                  float* __restrict__ out) {
    int gid = blockIdx.x * blockDim.x + threadIdx.x;
    int n   = gid >> 3;
    if (n >= N_NODES) return;
    int sub = gid & 7;

    int beg = __ldg(&starts[n]);
    int end = __ldg(&starts[n + 1]);

    __half* ap = &acc[(size_t)n * ACC_COLS + sub * 8];
    uint4 aw = *(const uint4*)ap;
    float4 a0 = make_float4(0.f, 0.f, 0.f, 0.f), a1 = a0;
    add8(a0, a1, aw);   // self-path from gemm cb0

    int i = beg;
    for (; i + 3 < end; i += 4) {
        int o0 = __ldg(&elist[i]);
        int o1 = __ldg(&elist[i + 1]);
        int o2 = __ldg(&elist[i + 2]);
        int o3 = __ldg(&elist[i + 3]);
        uint4 g0 = *(const uint4*)&msg[(size_t)o0 + sub * 8];
        uint4 g1 = *(const uint4*)&msg[(size_t)o1 + sub * 8];
        uint4 g2 = *(const uint4*)&msg[(size_t)o2 + sub * 8];
        uint4 g3 = *(const uint4*)&msg[(size_t)o3 + sub * 8];
        add8(a0, a1, g0); add8(a0, a1, g1);
        add8(a0, a1, g2); add8(a0, a1, g3);
    }
    for (; i < end; i++) {
        int o0 = __ldg(&elist[i]);
        uint4 g0 = *(const uint4*)&msg[(size_t)o0 + sub * 8];
        add8(a0, a1, g0);
    }

    a0.x = fmaxf(a0.x, 0.f); a0.y = fmaxf(a0.y, 0.f);
    a0.z = fmaxf(a0.z, 0.f); a0.w = fmaxf(a0.w, 0.f);
    a1.x = fmaxf(a1.x, 0.f); a1.y = fmaxf(a1.y, 0.f);
    a1.z = fmaxf(a1.z, 0.f); a1.w = fmaxf(a1.w, 0.f);

    if (MODE == 0) {
        __half h[8];
        h[0] = __float2half_rn(a0.x); h[1] = __float2half_rn(a0.y);
        h[2] = __float2half_rn(a0.z); h[3] = __float2half_rn(a0.w);
        h[4] = __float2half_rn(a1.x); h[5] = __float2half_rn(a1.y);
        h[6] = __float2half_rn(a1.z); h[7] = __float2half_rn(a1.w);
        *(uint4*)ap = *(const uint4*)h;
    } else {
        float r[8] = {a0.x, a0.y, a0.z, a0.w, a1.x, a1.y, a1.z, a1.w};
#pragma unroll
        for (int j = 0; j < 8; j++)
            r[j] = 1.f / (1.f + __expf(-r[j]));
        float4* op = (float4*)&out[(size_t)n * ACC_COLS + sub * 8];
        op[0] = make_float4(r[0], r[1], r[2], r[3]);
        op[1] = make_float4(r[4], r[5], r[6], r[7]);
    }
}

// ---------------------------------------------------------------------------
extern "C" void kernel_launch(void* const* d_in, const int* in_sizes, int n_in,
                              void* d_out, int out_size) {
    const float* node_emb = (const float*)d_in[0];
    const void*  src      = d_in[1];
    const void*  dst      = d_in[2];
    const float* W1       = (const float*)d_in[3];
    const float* Wself1   = (const float*)d_in[4];
    const float* W2       = (const float*)d_in[5];
    const float* Wself2   = (const float*)d_in[6];
    float*       out      = (float*)d_out;

    __half *emb, *acc1, *acc2, *msg1, *msg2, *B1, *B2;
    int *counts, *starts, *cursor, *bsum, *elist;
    cudaGetSymbolAddress((void**)&emb, g_emb);
    cudaGetSymbolAddress((void**)&acc1, g_acc1);
    cudaGetSymbolAddress((void**)&acc2, g_acc2);
    cudaGetSymbolAddress((void**)&msg1, g_msg1);
    cudaGetSymbolAddress((void**)&msg2, g_msg2);
    cudaGetSymbolAddress((void**)&B1, g_B1);
    cudaGetSymbolAddress((void**)&B2, g_B2);
    cudaGetSymbolAddress((void**)&counts, g_counts);
    cudaGetSymbolAddress((void**)&starts, g_starts);
    cudaGetSymbolAddress((void**)&cursor, g_cursor);
    cudaGetSymbolAddress((void**)&bsum, g_bsum);
    cudaGetSymbolAddress((void**)&elist, g_elist);

    // One-time host-side stream/event objects (no device memory).
    static cudaStream_t s2 = nullptr;
    static cudaEvent_t evFork = nullptr, evJoin = nullptr;
    if (s2 == nullptr) {
        cudaStreamCreateWithFlags(&s2, cudaStreamNonBlocking);
        cudaEventCreateWithFlags(&evFork, cudaEventDisableTiming);
        cudaEventCreateWithFlags(&evJoin, cudaEventDisableTiming);
    }

    const int nb1024 = (N_NODES + 1023) / 1024;   // 98
    const int mblocks = (N_NODES + 127) / 128;    // 782
    const int ablocks = (N_NODES * 8 + 255) / 256;

    // ---- fork: edge-list build on side stream (independent of branch A)
    cudaEventRecord(evFork, 0);
    cudaStreamWaitEvent(s2, evFork, 0);
    zero_sniff_kernel<<<ZB, 256, 0, s2>>>((const unsigned int*)src, counts);
    count_kernel<<<EB4, 256, 0, s2>>>(dst, counts);
    scan1_kernel<<<nb1024, 256, 0, s2>>>(counts, starts, bsum);
    scan3m_kernel<<<(N_NODES + 256) / 256, 256, 0, s2>>>(starts, cursor, bsum);
    fill_kernel<<<EB4, 256, 0, s2>>>(src, dst, cursor, elist);
    cudaEventRecord(evJoin, s2);

    // ---- branch A: convert + weights, then layer-1 GEMM
    conv_prep_kernel<<<CONVB + PREPB, 256>>>(node_emb, emb, W1, Wself1, W2, Wself2, B1, B2);
    gemm_mma_kernel<2><<<dim3(5, mblocks), 256>>>(emb, 128, B1, acc1, msg1);

    // ---- join: aggregation needs starts/elist
    cudaStreamWaitEvent(0, evJoin, 0);
    agg_kernel<0><<<ablocks, 256>>>(starts, elist, msg1, acc1, nullptr);

    // Layer 2: acc2/msg2 = acc1(fp16) @ Wc2; aggregate + relu + sigmoid -> out
    gemm_mma_kernel<1><<<dim3(5, mblocks), 256>>>(acc1, ACC_COLS, B2, acc2, msg2);
    agg_kernel<1><<<ablocks, 256>>>(starts, elist, msg2, acc2, out);
}